// round 14
// baseline (speedup 1.0000x reference)
#include <cuda_runtime.h>
#include <cuda_bf16.h>
#include <math.h>
#include <stdint.h>

#define SEQ   1024
#define HID   4096
#define NH    32
#define HD    128
#define INTER 11008
#define NL    2

typedef __nv_bfloat16 bf16;

// ---------------- scratch (device globals; no allocations allowed) ----------
__device__ float g_o[SEQ * HID];
__device__ float g_qkv[SEQ * 3 * HID];
__device__ float g_f[(size_t)SEQ * 2 * INTER];     // fused gate|up output

__device__ bf16 g_yhi[SEQ * HID],  g_ylo[SEQ * HID];
__device__ bf16 g_qhi[SEQ * HID],  g_qlo[SEQ * HID];
__device__ bf16 g_khi[SEQ * HID],  g_klo[SEQ * HID];
__device__ bf16 g_vthi[SEQ * HID], g_vtlo[SEQ * HID];
__device__ bf16 g_ghi[SEQ * INTER], g_glo[SEQ * INTER];

// ======================= helpers ==============================
__device__ __forceinline__ uint32_t smem_u32(const void* p) {
    uint32_t a;
    asm("{ .reg .u64 t; cvta.to.shared.u64 t, %1; cvt.u32.u64 %0, t; }" : "=r"(a) : "l"(p));
    return a;
}

__device__ __forceinline__ void ldsm_x4(uint32_t* r, uint32_t addr) {
    asm volatile("ldmatrix.sync.aligned.m8n8.x4.shared.b16 {%0,%1,%2,%3}, [%4];"
                 : "=r"(r[0]), "=r"(r[1]), "=r"(r[2]), "=r"(r[3]) : "r"(addr));
}

__device__ __forceinline__ void mma_bf16(float* c, const uint32_t* a, uint32_t b0, uint32_t b1) {
    asm volatile(
        "mma.sync.aligned.m16n8k16.row.col.f32.bf16.bf16.f32 "
        "{%0,%1,%2,%3}, {%4,%5,%6,%7}, {%8,%9}, {%0,%1,%2,%3};"
        : "+f"(c[0]), "+f"(c[1]), "+f"(c[2]), "+f"(c[3])
        : "r"(a[0]), "r"(a[1]), "r"(a[2]), "r"(a[3]), "r"(b0), "r"(b1));
}

#define CP16(dst, src) asm volatile("cp.async.cg.shared.global [%0], [%1], 16;" :: "r"(dst), "l"(src))
#define CP_COMMIT()    asm volatile("cp.async.commit_group;" ::: "memory")
#define CP_WAIT1()     asm volatile("cp.async.wait_group 1;" ::: "memory")
#define CP_WAIT0()     asm volatile("cp.async.wait_group 0;" ::: "memory")

__device__ __forceinline__ void split2(float x, bf16& h, bf16& l) {
    h = __float2bfloat16(x);
    l = __float2bfloat16(x - __bfloat162float(h));
}

__device__ __forceinline__ uint32_t pk(bf16 a, bf16 b) {
    return (uint32_t)__bfloat16_as_ushort(a) | ((uint32_t)__bfloat16_as_ushort(b) << 16);
}

#define ROWB 80

// term-major MMA block for one mt: 4x hh, 4x lh, 4x hl
#define MMA_TERM_MAJOR(accmt, ah, al, bh, bl)                                   \
    do {                                                                        \
        _Pragma("unroll")                                                       \
        for (int nt = 0; nt < 4; nt++)                                          \
            mma_bf16((accmt)[nt], ah, bh[nt >> 1][(nt & 1) * 2],                \
                     bh[nt >> 1][(nt & 1) * 2 + 1]);                            \
        _Pragma("unroll")                                                       \
        for (int nt = 0; nt < 4; nt++)                                          \
            mma_bf16((accmt)[nt], al, bh[nt >> 1][(nt & 1) * 2],                \
                     bh[nt >> 1][(nt & 1) * 2 + 1]);                            \
        _Pragma("unroll")                                                       \
        for (int nt = 0; nt < 4; nt++)                                          \
            mma_bf16((accmt)[nt], ah, bl[nt >> 1][(nt & 1) * 2],                \
                     bl[nt >> 1][(nt & 1) * 2 + 1]);                            \
    } while (0)

// ======= WEIGHT GEMM: 256x64 CTA, 256 thr, 2-stage, 2 CTAs/SM ===============
#define NTW    256
#define W_ATILE  (256 * ROWB)                 // 20480 B per A half
#define W_BTILE  (64 * ROWB)                  // 5120 B per B half
#define W_STAGEB (2 * W_ATILE + 2 * W_BTILE)  // 51200 B
#define W_SMEM   (2 * W_STAGEB)               // 102400 B -> 2 CTAs/SM

__device__ __forceinline__ void w_a_stage_load(
    uint32_t sdst, const bf16* __restrict__ Ahi, const bf16* __restrict__ Alo,
    int lda, int k0, int bm, int tid)
{
    #pragma unroll
    for (int i = 0; i < 4; i++) {
        int idx = tid + i * NTW;
        int r = idx >> 2, seg = (idx & 3) * 8;
        uint32_t so = sdst + (uint32_t)r * ROWB + (uint32_t)seg * 2;
        long long g = (long long)(bm + r) * lda + k0 + seg;
        CP16(so,           Ahi + g);
        CP16(so + W_ATILE, Alo + g);
    }
}

__global__ void __launch_bounds__(NTW, 2)
gemm_wsplit(const bf16* __restrict__ Ahi, const bf16* __restrict__ Alo,
            const float* __restrict__ B1, const float* __restrict__ B2, int N1,
            float* __restrict__ C, int K, int lda, int ldb, int ldc)
{
    extern __shared__ char smem[];
    const int tid = threadIdx.x;
    const int lane = tid & 31;
    const int wid = tid >> 5;
    const int wm = wid & 3;           // 0..3 (64-row quadrant)
    const int wn = wid >> 2;          // 0..1 (32-col half)

    const int bm = blockIdx.x * 256;
    const int bn = blockIdx.y * 64;

    const float* W = (bn < N1) ? (B1 + (long long)bn * ldb)
                               : (B2 + (long long)(bn - N1) * ldb);

    const uint32_t sb = smem_u32(smem);
    const int nk = K / 32;

    // B loader: 4 threads per row, 8 fp32 each (64 rows x 32 cols)
    const int br = tid >> 2;
    const int bc = (tid & 3) * 8;
    const float* Wrow = W + (long long)br * ldb + bc;
    const uint32_t bsts = 2 * W_ATILE + (uint32_t)br * ROWB + (uint32_t)bc * 2;

    const uint32_t aOff = (uint32_t)(wm * 64 + (lane & 15)) * ROWB + (uint32_t)(lane >> 4) * 16;
    const uint32_t bOff = (uint32_t)(wn * 32 + (((lane >> 4) << 3) | (lane & 7))) * ROWB
                        + (uint32_t)((lane >> 3) & 1) * 16;

    float acc[4][4][4];
    #pragma unroll
    for (int mt = 0; mt < 4; mt++)
        #pragma unroll
        for (int nt = 0; nt < 4; nt++)
            #pragma unroll
            for (int i = 0; i < 4; i++) acc[mt][nt][i] = 0.f;

    float4 rB[2];

    // ---- prologue: B(0) LDG+convert into stage 0; A(0) cp.async; prefetch B(1)
    rB[0] = *reinterpret_cast<const float4*>(Wrow);
    rB[1] = *reinterpret_cast<const float4*>(Wrow + 4);
    {
        bf16 h0,h1,h2,h3,l0,l1,l2,l3;
        #pragma unroll
        for (int v = 0; v < 2; v++) {
            split2(rB[v].x, h0, l0); split2(rB[v].y, h1, l1);
            split2(rB[v].z, h2, l2); split2(rB[v].w, h3, l3);
            *reinterpret_cast<uint2*>(smem + bsts + v * 8) = make_uint2(pk(h0,h1), pk(h2,h3));
            *reinterpret_cast<uint2*>(smem + bsts + W_BTILE + v * 8) = make_uint2(pk(l0,l1), pk(l2,l3));
        }
    }
    w_a_stage_load(sb, Ahi, Alo, lda, 0, bm, tid);
    CP_COMMIT();
    if (nk > 1) {
        rB[0] = *reinterpret_cast<const float4*>(Wrow + 32);
        rB[1] = *reinterpret_cast<const float4*>(Wrow + 36);
    }

    for (int j = 0; j < nk; j++) {
        if (j + 1 < nk) {
            w_a_stage_load(sb + (uint32_t)((j + 1) & 1) * W_STAGEB, Ahi, Alo, lda, (j + 1) * 32, bm, tid);
            CP_COMMIT();
            CP_WAIT1();
        } else {
            CP_WAIT0();
        }
        __syncthreads();

        const uint32_t st = sb + (uint32_t)(j & 1) * W_STAGEB;
        #pragma unroll
        for (int kk = 0; kk < 2; kk++) {
            uint32_t bh[2][4], bl[2][4];
            #pragma unroll
            for (int n2 = 0; n2 < 2; n2++) {
                uint32_t base = st + bOff + 2 * W_ATILE + (uint32_t)n2 * (16 * ROWB) + (uint32_t)kk * 32;
                ldsm_x4(bh[n2], base);
                ldsm_x4(bl[n2], base + W_BTILE);
            }
            #pragma unroll
            for (int mt = 0; mt < 4; mt++) {
                uint32_t ah[4], al[4];
                uint32_t base = st + aOff + (uint32_t)mt * (16 * ROWB) + (uint32_t)kk * 32;
                ldsm_x4(ah, base);
                ldsm_x4(al, base + W_ATILE);
                MMA_TERM_MAJOR(acc[mt], ah, al, bh, bl);
            }
        }

        if (j + 1 < nk) {
            uint32_t dst = (uint32_t)((j + 1) & 1) * W_STAGEB + bsts;
            bf16 h0,h1,h2,h3,l0,l1,l2,l3;
            #pragma unroll
            for (int v = 0; v < 2; v++) {
                split2(rB[v].x, h0, l0); split2(rB[v].y, h1, l1);
                split2(rB[v].z, h2, l2); split2(rB[v].w, h3, l3);
                *reinterpret_cast<uint2*>(smem + dst + v * 8) = make_uint2(pk(h0,h1), pk(h2,h3));
                *reinterpret_cast<uint2*>(smem + dst + W_BTILE + v * 8) = make_uint2(pk(l0,l1), pk(l2,l3));
            }
        }
        if (j + 2 < nk) {
            const float* p = Wrow + (j + 2) * 32;
            rB[0] = *reinterpret_cast<const float4*>(p);
            rB[1] = *reinterpret_cast<const float4*>(p + 4);
        }
        __syncthreads();
    }

    const int gr = lane >> 2;
    const int gc = (lane & 3) * 2;
    #pragma unroll
    for (int mt = 0; mt < 4; mt++) {
        int row0 = bm + wm * 64 + mt * 16 + gr;
        #pragma unroll
        for (int nt = 0; nt < 4; nt++) {
            int c = bn + wn * 32 + nt * 8 + gc;
            *reinterpret_cast<float2*>(C + (long long)row0 * ldc + c) =
                make_float2(acc[mt][nt][0], acc[mt][nt][1]);
            *reinterpret_cast<float2*>(C + (long long)(row0 + 8) * ldc + c) =
                make_float2(acc[mt][nt][2], acc[mt][nt][3]);
        }
    }
}

// =================== FUSED FLASH ATTENTION (unchanged) ======================
#define F_CHT  (128 * ROWB)            // 10240 B: one 128x32 bf16 tile
#define F_STGB (2 * F_CHT)             // 20480 B: hi + lo
#define F_QSZ  (4 * F_STGB)            // 81920 B: 4 hd-chunks of Q
#define F_SMEM (F_QSZ + 2 * F_STGB)    // 122880 B

__device__ __forceinline__ void f_load_chunk(
    uint32_t sdst, const bf16* __restrict__ hi_, const bf16* __restrict__ lo_,
    long long rowstride, long long base, int tid)
{
    #pragma unroll
    for (int i = 0; i < 2; i++) {
        int idx = tid + i * 256;
        int r = idx >> 2, seg = (idx & 3) * 8;
        uint32_t so = sdst + (uint32_t)r * ROWB + (uint32_t)seg * 2;
        long long g = base + (long long)r * rowstride + seg;
        CP16(so,         hi_ + g);
        CP16(so + F_CHT, lo_ + g);
    }
}

__global__ void __launch_bounds__(256, 1)
flash_attn(const bf16* __restrict__ qhi, const bf16* __restrict__ qlo,
           const bf16* __restrict__ khi, const bf16* __restrict__ klo,
           const bf16* __restrict__ vthi, const bf16* __restrict__ vtlo,
           bf16* __restrict__ yhi, bf16* __restrict__ ylo)
{
    extern __shared__ char smem[];
    const int tid = threadIdx.x;
    const int lane = tid & 31;
    const int wm = tid >> 5;
    const int head = blockIdx.y;
    const int qb = (SEQ / 128 - 1) - blockIdx.x;

    const uint32_t sb = smem_u32(smem);
    const int T = (qb + 1) * 8;

    const uint32_t aOffQ = (uint32_t)(wm * 16 + (lane & 15)) * ROWB + (uint32_t)(lane >> 4) * 16;
    const uint32_t bOffB = (uint32_t)(((lane >> 4) << 3) | (lane & 7)) * ROWB
                         + (uint32_t)((lane >> 3) & 1) * 16;

    const int gr = lane >> 2;
    const int gc = (lane & 3) * 2;

    float acc_s[16][4];
    float acc_o[16][4];
    #pragma unroll
    for (int nt = 0; nt < 16; nt++)
        #pragma unroll
        for (int i = 0; i < 4; i++) acc_o[nt][i] = 0.f;
    float m0 = -1e30f, m1 = -1e30f, l0 = 0.f, l1 = 0.f;

    {
        long long qbase = ((long long)head * SEQ + qb * 128) * HD;
        #pragma unroll
        for (int c = 0; c < 4; c++)
            f_load_chunk(sb + (uint32_t)c * F_STGB, qhi, qlo, HD, qbase + c * 32, tid);
    }
    f_load_chunk(sb + F_QSZ, khi, klo, HD, ((long long)head * SEQ) * HD, tid);
    CP_COMMIT();

    const float scale = 0.088388347648318447f;

    for (int t = 0; t < T; t++) {
        if (t + 1 < T) {
            int jn = (t + 1) >> 3, cn = (t + 1) & 7;
            uint32_t sdst = sb + F_QSZ + (uint32_t)((t + 1) & 1) * F_STGB;
            if (cn < 4)
                f_load_chunk(sdst, khi, klo, HD,
                             ((long long)head * SEQ + jn * 128) * HD + cn * 32, tid);
            else
                f_load_chunk(sdst, vthi, vtlo, SEQ,
                             (long long)head * HD * SEQ + jn * 128 + (cn - 4) * 32, tid);
            CP_COMMIT();
            CP_WAIT1();
        } else {
            CP_WAIT0();
        }
        __syncthreads();

        const int jb = t >> 3, c = t & 7;
        const uint32_t st = sb + F_QSZ + (uint32_t)(t & 1) * F_STGB;

        if (c < 4) {
            if (c == 0) {
                #pragma unroll
                for (int nt = 0; nt < 16; nt++)
                    #pragma unroll
                    for (int i = 0; i < 4; i++) acc_s[nt][i] = 0.f;
            }
            const uint32_t qaddr = sb + (uint32_t)c * F_STGB + aOffQ;
            #pragma unroll
            for (int kk = 0; kk < 2; kk++) {
                uint32_t ah[4], al[4];
                ldsm_x4(ah, qaddr + kk * 32);
                ldsm_x4(al, qaddr + F_CHT + kk * 32);
                #pragma unroll
                for (int half = 0; half < 2; half++) {
                    uint32_t bh[4][4], bl[4][4];
                    #pragma unroll
                    for (int g = 0; g < 4; g++) {
                        uint32_t ba = st + bOffB + (uint32_t)(half * 4 + g) * (16 * ROWB) + kk * 32;
                        ldsm_x4(bh[g], ba);
                        ldsm_x4(bl[g], ba + F_CHT);
                    }
                    #pragma unroll
                    for (int g = 0; g < 4; g++)
                        #pragma unroll
                        for (int sub = 0; sub < 2; sub++) {
                            int nt = (half * 4 + g) * 2 + sub;
                            uint32_t b0 = bh[g][sub * 2], b1 = bh[g][sub * 2 + 1];
                            mma_bf16(acc_s[nt], ah, b0, b1);
                            mma_bf16(acc_s[nt], al, b0, b1);
                            mma_bf16(acc_s[nt], ah, bl[g][sub * 2], bl[g][sub * 2 + 1]);
                        }
                }
            }
        } else {
            if (c == 4) {
                int row0 = qb * 128 + wm * 16 + gr;
                int row1 = row0 + 8;
                if (jb == qb) {
                    #pragma unroll
                    for (int nt = 0; nt < 16; nt++) {
                        int c0 = jb * 128 + nt * 8 + gc;
                        if (c0     > row0) acc_s[nt][0] = -1e30f;
                        if (c0 + 1 > row0) acc_s[nt][1] = -1e30f;
                        if (c0     > row1) acc_s[nt][2] = -1e30f;
                        if (c0 + 1 > row1) acc_s[nt][3] = -1e30f;
                    }
                }
                float mx0 = -1e30f, mx1 = -1e30f;
                #pragma unroll
                for (int nt = 0; nt < 16; nt++) {
                    mx0 = fmaxf(mx0, fmaxf(acc_s[nt][0], acc_s[nt][1]));
                    mx1 = fmaxf(mx1, fmaxf(acc_s[nt][2], acc_s[nt][3]));
                }
                mx0 = fmaxf(mx0, __shfl_xor_sync(0xffffffffu, mx0, 1));
                mx0 = fmaxf(mx0, __shfl_xor_sync(0xffffffffu, mx0, 2));
                mx1 = fmaxf(mx1, __shfl_xor_sync(0xffffffffu, mx1, 1));
                mx1 = fmaxf(mx1, __shfl_xor_sync(0xffffffffu, mx1, 2));
                float mn0 = fmaxf(m0, mx0 * scale);
                float mn1 = fmaxf(m1, mx1 * scale);
                float r0 = expf(m0 - mn0), r1 = expf(m1 - mn1);
                m0 = mn0; m1 = mn1;
                float s0 = 0.f, s1 = 0.f;
                #pragma unroll
                for (int nt = 0; nt < 16; nt++) {
                    float p0 = expf(acc_s[nt][0] * scale - mn0); acc_s[nt][0] = p0; s0 += p0;
                    float p1 = expf(acc_s[nt][1] * scale - mn0); acc_s[nt][1] = p1; s0 += p1;
                    float p2 = expf(acc_s[nt][2] * scale - mn1); acc_s[nt][2] = p2; s1 += p2;
                    float p3 = expf(acc_s[nt][3] * scale - mn1); acc_s[nt][3] = p3; s1 += p3;
                }
                s0 += __shfl_xor_sync(0xffffffffu, s0, 1);
                s0 += __shfl_xor_sync(0xffffffffu, s0, 2);
                s1 += __shfl_xor_sync(0xffffffffu, s1, 1);
                s1 += __shfl_xor_sync(0xffffffffu, s1, 2);
                l0 = l0 * r0 + s0;
                l1 = l1 * r1 + s1;
                #pragma unroll
                for (int nt = 0; nt < 16; nt++) {
                    acc_o[nt][0] *= r0; acc_o[nt][1] *= r0;
                    acc_o[nt][2] *= r1; acc_o[nt][3] *= r1;
                }
            }
            const int cc = c - 4;
            #pragma unroll
            for (int kk = 0; kk < 2; kk++) {
                int t16 = 2 * cc + kk;
                const float* p0 = acc_s[2 * t16];
                const float* p1 = acc_s[2 * t16 + 1];
                uint32_t ah[4], al[4];
                bf16 ha, hb, la, lb;
                split2(p0[0], ha, la); split2(p0[1], hb, lb); ah[0] = pk(ha, hb); al[0] = pk(la, lb);
                split2(p0[2], ha, la); split2(p0[3], hb, lb); ah[1] = pk(ha, hb); al[1] = pk(la, lb);
                split2(p1[0], ha, la); split2(p1[1], hb, lb); ah[2] = pk(ha, hb); al[2] = pk(la, lb);
                split2(p1[2], ha, la); split2(p1[3], hb, lb); ah[3] = pk(ha, hb); al[3] = pk(la, lb);
                #pragma unroll
                for (int half = 0; half < 2; half++) {
                    uint32_t bh[4][4], bl[4][4];
                    #pragma unroll
                    for (int g = 0; g < 4; g++) {
                        uint32_t ba = st + bOffB + (uint32_t)(half * 4 + g) * (16 * ROWB) + kk * 32;
                        ldsm_x4(bh[g], ba);
                        ldsm_x4(bl[g], ba + F_CHT);
                    }
                    #pragma unroll
                    for (int g = 0; g < 4; g++)
                        #pragma unroll
                        for (int sub = 0; sub < 2; sub++) {
                            int nt = (half * 4 + g) * 2 + sub;
                            uint32_t b0 = bh[g][sub * 2], b1 = bh[g][sub * 2 + 1];
                            mma_bf16(acc_o[nt], ah, b0, b1);
                            mma_bf16(acc_o[nt], al, b0, b1);
                            mma_bf16(acc_o[nt], ah, bl[g][sub * 2], bl[g][sub * 2 + 1]);
                        }
                }
            }
        }
        __syncthreads();
    }

    float li0 = 1.f / l0, li1 = 1.f / l1;
    int row0 = qb * 128 + wm * 16 + gr;
    #pragma unroll
    for (int nt = 0; nt < 16; nt++) {
        int col = head * HD + nt * 8 + gc;
        bf16 ha, hb, la, lb;
        split2(acc_o[nt][0] * li0, ha, la); split2(acc_o[nt][1] * li0, hb, lb);
        *reinterpret_cast<uint32_t*>(yhi + (long long)row0 * HID + col) = pk(ha, hb);
        *reinterpret_cast<uint32_t*>(ylo + (long long)row0 * HID + col) = pk(la, lb);
        split2(acc_o[nt][2] * li1, ha, la); split2(acc_o[nt][3] * li1, hb, lb);
        *reinterpret_cast<uint32_t*>(yhi + (long long)(row0 + 8) * HID + col) = pk(ha, hb);
        *reinterpret_cast<uint32_t*>(ylo + (long long)(row0 + 8) * HID + col) = pk(la, lb);
    }
}

// ---------------- RMSNorm with fused split ----------------
__global__ void __launch_bounds__(256) rmsnorm_split_kernel(
    const float* __restrict__ x, const float* __restrict__ w,
    bf16* __restrict__ yhi, bf16* __restrict__ ylo)
{
    int s = blockIdx.x;
    const float* rowp = x + (long long)s * HID;
    int tid = threadIdx.x;

    float ss = 0.f;
    for (int i = tid; i < HID; i += 256) { float v = rowp[i]; ss += v * v; }
    __shared__ float red[256];
    red[tid] = ss; __syncthreads();
    for (int st = 128; st > 0; st >>= 1) { if (tid < st) red[tid] += red[tid + st]; __syncthreads(); }
    float inv = rsqrtf(red[0] / (float)HID + 1e-6f);

    bf16* oh = yhi + (long long)s * HID;
    bf16* ol = ylo + (long long)s * HID;
    for (int i = tid; i < HID; i += 256) {
        float v = rowp[i] * inv * w[i];
        bf16 h, l; split2(v, h, l);
        oh[i] = h; ol[i] = l;
    }
}

// ------------ fused residual add + RMSNorm + split (h updated) -------------
__global__ void __launch_bounds__(256) add_rms_split_kernel(
    float* __restrict__ h, const float* __restrict__ o, const float* __restrict__ w,
    bf16* __restrict__ yhi, bf16* __restrict__ ylo)
{
    int s = blockIdx.x;
    long long base = (long long)s * HID;
    int tid = threadIdx.x;
    __shared__ float v[HID];
    __shared__ float red[256];

    float ss = 0.f;
    for (int i = tid; i < HID; i += 256) {
        float t = h[base + i] + o[base + i];
        h[base + i] = t;
        v[i] = t;
        ss += t * t;
    }
    red[tid] = ss; __syncthreads();
    for (int st = 128; st > 0; st >>= 1) { if (tid < st) red[tid] += red[tid + st]; __syncthreads(); }
    float inv = rsqrtf(red[0] / (float)HID + 1e-6f);

    bf16* oh = yhi + base;
    bf16* ol = ylo + base;
    for (int i = tid; i < HID; i += 256) {
        float t = v[i] * inv * w[i];
        bf16 hh, ll; split2(t, hh, ll);
        oh[i] = hh; ol[i] = ll;
    }
}

// -------- RoPE q/k + coalesced V transpose (per head, per 128-s tile) -------
__global__ void __launch_bounds__(256) rope_v_kernel(
    const float* __restrict__ qkv,
    const float* __restrict__ cosT, const float* __restrict__ sinT,
    const int* __restrict__ pos_ids,
    bf16* __restrict__ qhi, bf16* __restrict__ qlo,
    bf16* __restrict__ khi, bf16* __restrict__ klo,
    bf16* __restrict__ vthi, bf16* __restrict__ vtlo)
{
    extern __shared__ uint32_t T[];   // [128][129] packed (hi,lo)
    int head = blockIdx.x;
    int st = blockIdx.y * 128;
    int tid = threadIdx.x;

    for (int i = tid; i < 128 * 128; i += 256) {
        int sl = i >> 7, d = i & 127;
        int s = st + sl;
        int pos = pos_ids[s];
        if (pos < 0) pos = 0;
        if (pos >= SEQ) pos = SEQ - 1;
        const float* rowp = qkv + (long long)s * (3 * HID);
        int idx = head * HD + d;
        float qv = rowp[idx];
        float kv = rowp[HID + idx];
        float vv = rowp[2 * HID + idx];
        float qo = (d < 64) ? -rowp[idx + 64] : rowp[idx - 64];
        float ko = (d < 64) ? -rowp[HID + idx + 64] : rowp[HID + idx - 64];
        float cd = cosT[(long long)pos * HD + d];
        float sd = sinT[(long long)pos * HD + d];
        float qr = qv * cd + qo * sd;
        float kr = kv * cd + ko * sd;
        long long qi = ((long long)head * SEQ + s) * HD + d;
        bf16 hh, ll;
        split2(qr, hh, ll); qhi[qi] = hh; qlo[qi] = ll;
        split2(kr, hh, ll); khi[qi] = hh; klo[qi] = ll;
        split2(vv, hh, ll);
        T[sl * 129 + d] = pk(hh, ll);
    }
    __syncthreads();
    for (int i = tid; i < 128 * 128; i += 256) {
        int d = i >> 7, sl = i & 127;
        uint32_t p = T[sl * 129 + d];
        long long vi = ((long long)head * HD + d) * SEQ + st + sl;
        vthi[vi] = __ushort_as_bfloat16((unsigned short)(p & 0xFFFF));
        vtlo[vi] = __ushort_as_bfloat16((unsigned short)(p >> 16));
    }
}

// ---------------- elementwise ----------------
__global__ void __launch_bounds__(256) add_kernel(float* __restrict__ a, const float* __restrict__ b, int n)
{
    int i = blockIdx.x * 256 + threadIdx.x;
    if (i < n) a[i] += b[i];
}

__global__ void __launch_bounds__(256) silu_mul_split_kernel(
    const float* __restrict__ f, bf16* __restrict__ ghi, bf16* __restrict__ glo, int n)
{
    int i = blockIdx.x * 256 + threadIdx.x;
    if (i < n) {
        int s = i / INTER, c = i - s * INTER;
        long long base = (long long)s * (2 * INTER);
        float x = f[base + c];
        float v = x / (1.f + expf(-x)) * f[base + INTER + c];
        bf16 h, l; split2(v, h, l);
        ghi[i] = h; glo[i] = l;
    }
}

// ---------------- orchestration ----------------
static inline void launch_gemm_w(const bf16* Ahi, const bf16* Alo,
                                 const float* B1, const float* B2, int N1, float* C,
                                 int M, int N, int K, int lda, int ldb, int ldc)
{
    dim3 grid(M / 256, N / 64);
    gemm_wsplit<<<grid, NTW, W_SMEM>>>(Ahi, Alo, B1, B2, N1, C, K, lda, ldb, ldc);
}

extern "C" void kernel_launch(void* const* d_in, const int* in_sizes, int n_in,
                              void* d_out, int out_size)
{
    const float* x      = (const float*)d_in[0];
    const int*   pos    = (const int*)d_in[1];
    const float* qkv_w  = (const float*)d_in[2];
    const float* o_w    = (const float*)d_in[3];
    const float* gate_w = (const float*)d_in[4];
    const float* up_w   = (const float*)d_in[5];
    const float* down_w = (const float*)d_in[6];
    const float* ln1_w  = (const float*)d_in[7];
    const float* ln2_w  = (const float*)d_in[8];
    const float* cosT   = (const float*)d_in[9];
    const float* sinT   = (const float*)d_in[10];
    float* h = (float*)d_out;

    cudaFuncSetAttribute(gemm_wsplit, cudaFuncAttributeMaxDynamicSharedMemorySize, W_SMEM);
    cudaFuncSetAttribute(flash_attn, cudaFuncAttributeMaxDynamicSharedMemorySize, F_SMEM);
    cudaFuncSetAttribute(rope_v_kernel, cudaFuncAttributeMaxDynamicSharedMemorySize, 128 * 129 * 4);

    float *o, *qkv, *f;
    bf16 *yhi, *ylo, *qhi, *qlo, *khi, *klo, *vthi, *vtlo, *ghi, *glo;
    cudaGetSymbolAddress((void**)&o, g_o);
    cudaGetSymbolAddress((void**)&qkv, g_qkv);
    cudaGetSymbolAddress((void**)&f, g_f);
    cudaGetSymbolAddress((void**)&yhi, g_yhi);
    cudaGetSymbolAddress((void**)&ylo, g_ylo);
    cudaGetSymbolAddress((void**)&qhi, g_qhi);
    cudaGetSymbolAddress((void**)&qlo, g_qlo);
    cudaGetSymbolAddress((void**)&khi, g_khi);
    cudaGetSymbolAddress((void**)&klo, g_klo);
    cudaGetSymbolAddress((void**)&vthi, g_vthi);
    cudaGetSymbolAddress((void**)&vtlo, g_vtlo);
    cudaGetSymbolAddress((void**)&ghi, g_ghi);
    cudaGetSymbolAddress((void**)&glo, g_glo);

    cudaMemcpyAsync(h, x, sizeof(float) * SEQ * HID, cudaMemcpyDeviceToDevice, 0);

    const int nEl = SEQ * HID;
    const int nElI = SEQ * INTER;
    const int BIGN = 1 << 30;

    rmsnorm_split_kernel<<<SEQ, 256>>>(h, ln1_w, yhi, ylo);

    for (int L = 0; L < NL; L++) {
        const float* qw = qkv_w  + (size_t)L * 3 * HID * HID;
        const float* ow = o_w    + (size_t)L * HID * HID;
        const float* gw = gate_w + (size_t)L * INTER * HID;
        const float* uw = up_w   + (size_t)L * INTER * HID;
        const float* dw = down_w + (size_t)L * HID * INTER;

        // ---- attention ----
        launch_gemm_w(yhi, ylo, qw, qw, BIGN, qkv, SEQ, 3 * HID, HID, HID, HID, 3 * HID);

        rope_v_kernel<<<dim3(NH, SEQ / 128), 256, 128 * 129 * 4>>>(
            qkv, cosT, sinT, pos, qhi, qlo, khi, klo, vthi, vtlo);

        flash_attn<<<dim3(SEQ / 128, NH), 256, F_SMEM>>>(
            qhi, qlo, khi, klo, vthi, vtlo, yhi, ylo);

        launch_gemm_w(yhi, ylo, ow, ow, BIGN, o, SEQ, HID, HID, HID, HID, HID);

        add_rms_split_kernel<<<SEQ, 256>>>(h, o, ln2_w + (size_t)L * HID, yhi, ylo);

        // ---- MLP: fused gate|up ----
        launch_gemm_w(yhi, ylo, gw, uw, INTER, f, SEQ, 2 * INTER, HID, HID, HID, 2 * INTER);

        silu_mul_split_kernel<<<nElI / 256, 256>>>(f, ghi, glo, nElI);

        launch_gemm_w(ghi, glo, dw, dw, BIGN, o, SEQ, HID, INTER, INTER, INTER, HID);

        if (L < NL - 1) {
            add_rms_split_kernel<<<SEQ, 256>>>(h, o, ln1_w + (size_t)(L + 1) * HID, yhi, ylo);
        } else {
            add_kernel<<<nEl / 256, 256>>>(h, o, nEl);
        }
    }
}

// round 15
// speedup vs baseline: 1.0470x; 1.0470x over previous
#include <cuda_runtime.h>
#include <cuda_bf16.h>
#include <math.h>
#include <stdint.h>

#define SEQ   1024
#define HID   4096
#define NH    32
#define HD    128
#define INTER 11008
#define NL    2

typedef __nv_bfloat16 bf16;

// ---------------- scratch (device globals; no allocations allowed) ----------
__device__ float g_y[SEQ * HID];
__device__ float g_o[SEQ * HID];
__device__ float g_qkv[SEQ * 3 * HID];
__device__ float g_sc[(size_t)NH * SEQ * SEQ];
__device__ float g_f[(size_t)SEQ * 2 * INTER];

__device__ bf16 g_yhi[SEQ * HID],  g_ylo[SEQ * HID];
__device__ bf16 g_qhi[SEQ * HID],  g_qlo[SEQ * HID];
__device__ bf16 g_khi[SEQ * HID],  g_klo[SEQ * HID];
__device__ bf16 g_vthi[SEQ * HID], g_vtlo[SEQ * HID];
__device__ bf16 g_phi[(size_t)NH * SEQ * SEQ], g_plo[(size_t)NH * SEQ * SEQ];
__device__ bf16 g_ghi[SEQ * INTER], g_glo[SEQ * INTER];

// ======================= helpers ==============================
__device__ __forceinline__ uint32_t smem_u32(const void* p) {
    uint32_t a;
    asm("{ .reg .u64 t; cvta.to.shared.u64 t, %1; cvt.u32.u64 %0, t; }" : "=r"(a) : "l"(p));
    return a;
}

__device__ __forceinline__ void ldsm_x4(uint32_t* r, uint32_t addr) {
    asm volatile("ldmatrix.sync.aligned.m8n8.x4.shared.b16 {%0,%1,%2,%3}, [%4];"
                 : "=r"(r[0]), "=r"(r[1]), "=r"(r[2]), "=r"(r[3]) : "r"(addr));
}

__device__ __forceinline__ void mma_bf16(float* c, const uint32_t* a, uint32_t b0, uint32_t b1) {
    asm volatile(
        "mma.sync.aligned.m16n8k16.row.col.f32.bf16.bf16.f32 "
        "{%0,%1,%2,%3}, {%4,%5,%6,%7}, {%8,%9}, {%0,%1,%2,%3};"
        : "+f"(c[0]), "+f"(c[1]), "+f"(c[2]), "+f"(c[3])
        : "r"(a[0]), "r"(a[1]), "r"(a[2]), "r"(a[3]), "r"(b0), "r"(b1));
}

#define CP16(dst, src) asm volatile("cp.async.cg.shared.global [%0], [%1], 16;" :: "r"(dst), "l"(src))
#define CP_COMMIT()    asm volatile("cp.async.commit_group;" ::: "memory")
#define CP_WAIT0()     asm volatile("cp.async.wait_group 0;" ::: "memory")

__device__ __forceinline__ void split2(float x, bf16& h, bf16& l) {
    h = __float2bfloat16(x);
    l = __float2bfloat16(x - __bfloat162float(h));
}

__device__ __forceinline__ uint32_t pk(bf16 a, bf16 b) {
    return (uint32_t)__bfloat16_as_ushort(a) | ((uint32_t)__bfloat16_as_ushort(b) << 16);
}

// term-major MMA block for one mt: 4x hh, 4x lh, 4x hl
#define MMA_TERM_MAJOR(accmt, ah, al, bh, bl)                                   \
    do {                                                                        \
        _Pragma("unroll")                                                       \
        for (int nt = 0; nt < 4; nt++)                                          \
            mma_bf16((accmt)[nt], ah, bh[nt >> 1][(nt & 1) * 2],                \
                     bh[nt >> 1][(nt & 1) * 2 + 1]);                            \
        _Pragma("unroll")                                                       \
        for (int nt = 0; nt < 4; nt++)                                          \
            mma_bf16((accmt)[nt], al, bh[nt >> 1][(nt & 1) * 2],                \
                     bh[nt >> 1][(nt & 1) * 2 + 1]);                            \
        _Pragma("unroll")                                                       \
        for (int nt = 0; nt < 4; nt++)                                          \
            mma_bf16((accmt)[nt], ah, bl[nt >> 1][(nt & 1) * 2],                \
                     bl[nt >> 1][(nt & 1) * 2 + 1]);                            \
    } while (0)

// ==== WEIGHT GEMM: 256x128, 512 thr, Kc=64, 2-stage, single sync/chunk ======
#define NTW    512
#define RW2    144                           // 128B data + 16B pad
#define W_AT   (256 * RW2)                   // 36864 per half
#define W_BT   (128 * RW2)                   // 18432 per half
#define W_STG  (2 * W_AT + 2 * W_BT)         // 110592
#define W_SMEM (2 * W_STG)                   // 221184

__device__ __forceinline__ void w_a_load64(
    uint32_t sdst, const bf16* __restrict__ Ahi, const bf16* __restrict__ Alo,
    int lda, int k0, int bm, int tid)
{
    #pragma unroll
    for (int i = 0; i < 4; i++) {
        int idx = tid + i * NTW;             // 0..2047
        int r = idx >> 3, u = idx & 7;
        uint32_t so = sdst + (uint32_t)r * RW2 + (uint32_t)u * 16;
        long long g = (long long)(bm + r) * lda + k0 + u * 8;
        CP16(so,        Ahi + g);
        CP16(so + W_AT, Alo + g);
    }
}

__global__ void __launch_bounds__(NTW, 1)
gemm_wsplit(const bf16* __restrict__ Ahi, const bf16* __restrict__ Alo,
            const float* __restrict__ B1, const float* __restrict__ B2, int N1,
            float* __restrict__ C, int K, int lda, int ldb, int ldc)
{
    extern __shared__ char smem[];
    const int tid = threadIdx.x;
    const int lane = tid & 31;
    const int wid = tid >> 5;
    const int wm = wid & 3;
    const int wn = wid >> 2;

    const int bm = blockIdx.x * 256;
    const int bn = blockIdx.y * 128;

    const float* W = (bn < N1) ? (B1 + (long long)bn * ldb)
                               : (B2 + (long long)(bn - N1) * ldb);

    const uint32_t sb = smem_u32(smem);
    const int nk = K / 64;

    // B loader: 4 threads per row, 16 fp32 each
    const int br = tid >> 2;
    const int bc = (tid & 3) * 16;
    const float* Wrow = W + (long long)br * ldb + bc;
    const uint32_t bsts = 2 * W_AT + (uint32_t)br * RW2 + (uint32_t)bc * 2;

    const uint32_t aOff = (uint32_t)(wm * 64 + (lane & 15)) * RW2 + (uint32_t)(lane >> 4) * 16;
    const uint32_t bOff = (uint32_t)(wn * 32 + (((lane >> 4) << 3) | (lane & 7))) * RW2
                        + (uint32_t)((lane >> 3) & 1) * 16;

    float acc[4][4][4];
    #pragma unroll
    for (int mt = 0; mt < 4; mt++)
        #pragma unroll
        for (int nt = 0; nt < 4; nt++)
            #pragma unroll
            for (int i = 0; i < 4; i++) acc[mt][nt][i] = 0.f;

    float4 rB[4];

    // ---- prologue: B(0) LDG+convert+STS stage0; A(0) cp.async; prefetch B(1)
    #pragma unroll
    for (int v = 0; v < 4; v++) rB[v] = *reinterpret_cast<const float4*>(Wrow + v * 4);
    {
        bf16 h0,h1,h2,h3,l0,l1,l2,l3;
        #pragma unroll
        for (int v = 0; v < 4; v++) {
            split2(rB[v].x, h0, l0); split2(rB[v].y, h1, l1);
            split2(rB[v].z, h2, l2); split2(rB[v].w, h3, l3);
            *reinterpret_cast<uint2*>(smem + bsts + v * 8) = make_uint2(pk(h0,h1), pk(h2,h3));
            *reinterpret_cast<uint2*>(smem + bsts + W_BT + v * 8) = make_uint2(pk(l0,l1), pk(l2,l3));
        }
    }
    w_a_load64(sb, Ahi, Alo, lda, 0, bm, tid);
    CP_COMMIT();
    if (nk > 1) {
        #pragma unroll
        for (int v = 0; v < 4; v++) rB[v] = *reinterpret_cast<const float4*>(Wrow + 64 + v * 4);
    }

    for (int j = 0; j < nk; j++) {
        CP_WAIT0();
        __syncthreads();           // stage j data visible; all warps done with iter j-1

        if (j + 1 < nk) {
            w_a_load64(sb + (uint32_t)((j + 1) & 1) * W_STG, Ahi, Alo, lda, (j + 1) * 64, bm, tid);
            CP_COMMIT();
        }

        const uint32_t st = sb + (uint32_t)(j & 1) * W_STG;
        #pragma unroll
        for (int kk = 0; kk < 4; kk++) {
            uint32_t bh[2][4], bl[2][4];
            #pragma unroll
            for (int n2 = 0; n2 < 2; n2++) {
                uint32_t base = st + bOff + 2 * W_AT + (uint32_t)n2 * (16 * RW2) + (uint32_t)kk * 32;
                ldsm_x4(bh[n2], base);
                ldsm_x4(bl[n2], base + W_BT);
            }
            #pragma unroll
            for (int mt = 0; mt < 4; mt++) {
                uint32_t ah[4], al[4];
                uint32_t base = st + aOff + (uint32_t)mt * (16 * RW2) + (uint32_t)kk * 32;
                ldsm_x4(ah, base);
                ldsm_x4(al, base + W_AT);
                MMA_TERM_MAJOR(acc[mt], ah, al, bh, bl);
            }
        }

        if (j + 1 < nk) {
            uint32_t dst = (uint32_t)((j + 1) & 1) * W_STG + bsts;
            bf16 h0,h1,h2,h3,l0,l1,l2,l3;
            #pragma unroll
            for (int v = 0; v < 4; v++) {
                split2(rB[v].x, h0, l0); split2(rB[v].y, h1, l1);
                split2(rB[v].z, h2, l2); split2(rB[v].w, h3, l3);
                *reinterpret_cast<uint2*>(smem + dst + v * 8) = make_uint2(pk(h0,h1), pk(h2,h3));
                *reinterpret_cast<uint2*>(smem + dst + W_BT + v * 8) = make_uint2(pk(l0,l1), pk(l2,l3));
            }
        }
        if (j + 2 < nk) {
            const float* p = Wrow + (j + 2) * 64;
            #pragma unroll
            for (int v = 0; v < 4; v++) rB[v] = *reinterpret_cast<const float4*>(p + v * 4);
        }
    }

    const int gr = lane >> 2;
    const int gc = (lane & 3) * 2;
    #pragma unroll
    for (int mt = 0; mt < 4; mt++) {
        int row0 = bm + wm * 64 + mt * 16 + gr;
        #pragma unroll
        for (int nt = 0; nt < 4; nt++) {
            int c = bn + wn * 32 + nt * 8 + gc;
            *reinterpret_cast<float2*>(C + (long long)row0 * ldc + c) =
                make_float2(acc[mt][nt][0], acc[mt][nt][1]);
            *reinterpret_cast<float2*>(C + (long long)(row0 + 8) * ldc + c) =
                make_float2(acc[mt][nt][2], acc[mt][nt][3]);
        }
    }
}

// === ATTENTION GEMM: 128x128, 256 thr, 2-stage, 2 CTAs/SM, single sync ======
#define NTA    256
#define ROWB   80
#define A_ATILE  (128 * ROWB)
#define A_BTILE  (128 * ROWB)
#define A_STAGEB (2 * A_ATILE + 2 * A_BTILE)  // 40960
#define A_SMEM   (2 * A_STAGEB)               // 81920

__device__ __forceinline__ void stage_load_ab(
    uint32_t sdst,
    const bf16* __restrict__ Ahi, const bf16* __restrict__ Alo,
    const bf16* __restrict__ Bhi, const bf16* __restrict__ Blo,
    int lda, int ldb, int k0, int bm, int bn, int tid)
{
    #pragma unroll
    for (int i = 0; i < 2; i++) {
        int idx = tid + i * NTA;
        int r = idx >> 2, seg = (idx & 3) * 8;
        uint32_t soA = sdst + (uint32_t)r * ROWB + (uint32_t)seg * 2;
        long long gA = (long long)(bm + r) * lda + k0 + seg;
        CP16(soA,           Ahi + gA);
        CP16(soA + A_ATILE, Alo + gA);
        uint32_t soB = sdst + 2 * A_ATILE + (uint32_t)r * ROWB + (uint32_t)seg * 2;
        long long gB = (long long)(bn + r) * ldb + k0 + seg;
        CP16(soB,           Bhi + gB);
        CP16(soB + A_BTILE, Blo + gB);
    }
}

__global__ void __launch_bounds__(NTA, 2)
gemm_bf16_split(const bf16* __restrict__ Ahi, const bf16* __restrict__ Alo,
                const bf16* __restrict__ Bhi, const bf16* __restrict__ Blo,
                float* __restrict__ C, int K, int lda, int ldb, int ldc,
                long long sA, long long sB, long long sC, int mode)
{
    extern __shared__ char smem[];
    const int tid = threadIdx.x;
    const int lane = tid & 31;
    const int wid = tid >> 5;
    const int wm = wid & 1;
    const int wn = wid >> 1;

    const int bm = blockIdx.x * 128;
    const int bn = blockIdx.y * 128;
    if (mode == 1 && bn >= bm + 128) return;

    Ahi += (long long)blockIdx.z * sA;
    Alo += (long long)blockIdx.z * sA;
    Bhi += (long long)blockIdx.z * sB;
    Blo += (long long)blockIdx.z * sB;
    C   += (long long)blockIdx.z * sC;

    int kend = (mode == 2) ? min(K, bm + 128) : K;
    const int nk = kend / 32;

    const uint32_t sb = smem_u32(smem);

    const uint32_t aOff = (uint32_t)(wm * 64 + (lane & 15)) * ROWB + (uint32_t)(lane >> 4) * 16;
    const uint32_t bOff = (uint32_t)(wn * 32 + (((lane >> 4) << 3) | (lane & 7))) * ROWB
                        + (uint32_t)((lane >> 3) & 1) * 16;

    float acc[4][4][4];
    #pragma unroll
    for (int mt = 0; mt < 4; mt++)
        #pragma unroll
        for (int nt = 0; nt < 4; nt++)
            #pragma unroll
            for (int i = 0; i < 4; i++) acc[mt][nt][i] = 0.f;

    stage_load_ab(sb, Ahi, Alo, Bhi, Blo, lda, ldb, 0, bm, bn, tid);
    CP_COMMIT();

    for (int j = 0; j < nk; j++) {
        CP_WAIT0();
        __syncthreads();

        if (j + 1 < nk) {
            stage_load_ab(sb + (uint32_t)((j + 1) & 1) * A_STAGEB,
                          Ahi, Alo, Bhi, Blo, lda, ldb, (j + 1) * 32, bm, bn, tid);
            CP_COMMIT();
        }

        const uint32_t st = sb + (uint32_t)(j & 1) * A_STAGEB;
        #pragma unroll
        for (int kk = 0; kk < 2; kk++) {
            uint32_t bh[2][4], bl[2][4];
            #pragma unroll
            for (int n2 = 0; n2 < 2; n2++) {
                uint32_t base = st + bOff + 2 * A_ATILE + (uint32_t)n2 * (16 * ROWB) + (uint32_t)kk * 32;
                ldsm_x4(bh[n2], base);
                ldsm_x4(bl[n2], base + A_BTILE);
            }
            #pragma unroll
            for (int mt = 0; mt < 4; mt++) {
                uint32_t ah[4], al[4];
                uint32_t base = st + aOff + (uint32_t)mt * (16 * ROWB) + (uint32_t)kk * 32;
                ldsm_x4(ah, base);
                ldsm_x4(al, base + A_ATILE);
                MMA_TERM_MAJOR(acc[mt], ah, al, bh, bl);
            }
        }
    }

    const int gr = lane >> 2;
    const int gc = (lane & 3) * 2;
    #pragma unroll
    for (int mt = 0; mt < 4; mt++) {
        int row0 = bm + wm * 64 + mt * 16 + gr;
        #pragma unroll
        for (int nt = 0; nt < 4; nt++) {
            int c = bn + wn * 32 + nt * 8 + gc;
            *reinterpret_cast<float2*>(C + (long long)row0 * ldc + c) =
                make_float2(acc[mt][nt][0], acc[mt][nt][1]);
            *reinterpret_cast<float2*>(C + (long long)(row0 + 8) * ldc + c) =
                make_float2(acc[mt][nt][2], acc[mt][nt][3]);
        }
    }
}

// ---------------- fp32 -> bf16 hi/lo split ----------------
__global__ void __launch_bounds__(256) split_kernel(
    const float* __restrict__ in, bf16* __restrict__ hi, bf16* __restrict__ lo, long long n)
{
    long long i = ((long long)blockIdx.x * 256 + threadIdx.x) * 4;
    if (i >= n) return;
    float4 v = *reinterpret_cast<const float4*>(in + i);
    bf16 h0, h1, h2, h3, l0, l1, l2, l3;
    split2(v.x, h0, l0); split2(v.y, h1, l1); split2(v.z, h2, l2); split2(v.w, h3, l3);
    *reinterpret_cast<uint2*>(hi + i) = make_uint2(pk(h0,h1), pk(h2,h3));
    *reinterpret_cast<uint2*>(lo + i) = make_uint2(pk(l0,l1), pk(l2,l3));
}

// ---------------- RMSNorm with fused split ----------------
__global__ void __launch_bounds__(256) rmsnorm_split_kernel(
    const float* __restrict__ x, const float* __restrict__ w,
    bf16* __restrict__ yhi, bf16* __restrict__ ylo)
{
    int s = blockIdx.x;
    const float* rowp = x + (long long)s * HID;
    int tid = threadIdx.x;

    float ss = 0.f;
    for (int i = tid; i < HID; i += 256) { float v = rowp[i]; ss += v * v; }
    __shared__ float red[256];
    red[tid] = ss; __syncthreads();
    for (int st = 128; st > 0; st >>= 1) { if (tid < st) red[tid] += red[tid + st]; __syncthreads(); }
    float inv = rsqrtf(red[0] / (float)HID + 1e-6f);

    bf16* oh = yhi + (long long)s * HID;
    bf16* ol = ylo + (long long)s * HID;
    for (int i = tid; i < HID; i += 256) {
        float v = rowp[i] * inv * w[i];
        bf16 h, l; split2(v, h, l);
        oh[i] = h; ol[i] = l;
    }
}

// ------------ fused residual add + RMSNorm + split ----------------
__global__ void __launch_bounds__(256) add_rms_split_kernel(
    float* __restrict__ h, const float* __restrict__ o, const float* __restrict__ w,
    bf16* __restrict__ yhi, bf16* __restrict__ ylo)
{
    int s = blockIdx.x;
    long long base = (long long)s * HID;
    int tid = threadIdx.x;
    __shared__ float v[HID];
    __shared__ float red[256];

    float ss = 0.f;
    for (int i = tid; i < HID; i += 256) {
        float t = h[base + i] + o[base + i];
        h[base + i] = t;
        v[i] = t;
        ss += t * t;
    }
    red[tid] = ss; __syncthreads();
    for (int st = 128; st > 0; st >>= 1) { if (tid < st) red[tid] += red[tid + st]; __syncthreads(); }
    float inv = rsqrtf(red[0] / (float)HID + 1e-6f);

    bf16* oh = yhi + base;
    bf16* ol = ylo + base;
    for (int i = tid; i < HID; i += 256) {
        float t = v[i] * inv * w[i];
        bf16 hh, ll; split2(t, hh, ll);
        oh[i] = hh; ol[i] = ll;
    }
}

// -------- RoPE q/k + coalesced V transpose ----------------
__global__ void __launch_bounds__(256) rope_v_kernel(
    const float* __restrict__ qkv,
    const float* __restrict__ cosT, const float* __restrict__ sinT,
    const int* __restrict__ pos_ids,
    bf16* __restrict__ qhi, bf16* __restrict__ qlo,
    bf16* __restrict__ khi, bf16* __restrict__ klo,
    bf16* __restrict__ vthi, bf16* __restrict__ vtlo)
{
    extern __shared__ uint32_t T[];
    int head = blockIdx.x;
    int st = blockIdx.y * 128;
    int tid = threadIdx.x;

    for (int i = tid; i < 128 * 128; i += 256) {
        int sl = i >> 7, d = i & 127;
        int s = st + sl;
        int pos = pos_ids[s];
        if (pos < 0) pos = 0;
        if (pos >= SEQ) pos = SEQ - 1;
        const float* rowp = qkv + (long long)s * (3 * HID);
        int idx = head * HD + d;
        float qv = rowp[idx];
        float kv = rowp[HID + idx];
        float vv = rowp[2 * HID + idx];
        float qo = (d < 64) ? -rowp[idx + 64] : rowp[idx - 64];
        float ko = (d < 64) ? -rowp[HID + idx + 64] : rowp[HID + idx - 64];
        float cd = cosT[(long long)pos * HD + d];
        float sd = sinT[(long long)pos * HD + d];
        float qr = qv * cd + qo * sd;
        float kr = kv * cd + ko * sd;
        long long qi = ((long long)head * SEQ + s) * HD + d;
        bf16 hh, ll;
        split2(qr, hh, ll); qhi[qi] = hh; qlo[qi] = ll;
        split2(kr, hh, ll); khi[qi] = hh; klo[qi] = ll;
        split2(vv, hh, ll);
        T[sl * 129 + d] = pk(hh, ll);
    }
    __syncthreads();
    for (int i = tid; i < 128 * 128; i += 256) {
        int d = i >> 7, sl = i & 127;
        uint32_t p = T[sl * 129 + d];
        long long vi = ((long long)head * HD + d) * SEQ + st + sl;
        vthi[vi] = __ushort_as_bfloat16((unsigned short)(p & 0xFFFF));
        vtlo[vi] = __ushort_as_bfloat16((unsigned short)(p >> 16));
    }
}

// ---------------- causal softmax with fused split ----------------
__global__ void __launch_bounds__(256) softmax_split_kernel(
    float* __restrict__ scores, bf16* __restrict__ phi, bf16* __restrict__ plo)
{
    int qrow = blockIdx.x;
    int head = blockIdx.y;
    long long off = ((long long)head * SEQ + qrow) * SEQ;
    float* rowp = scores + off;
    bf16* oh = phi + off;
    bf16* ol = plo + off;
    int n = qrow + 1;
    int tid = threadIdx.x;
    const float scale = 0.088388347648318447f;

    __shared__ float red[256];

    float m = -3.4e38f;
    for (int i = tid; i < n; i += 256) m = fmaxf(m, rowp[i] * scale);
    red[tid] = m; __syncthreads();
    for (int st = 128; st > 0; st >>= 1) { if (tid < st) red[tid] = fmaxf(red[tid], red[tid + st]); __syncthreads(); }
    m = red[0]; __syncthreads();

    float sum = 0.f;
    for (int i = tid; i < n; i += 256) {
        float e = expf(rowp[i] * scale - m);
        rowp[i] = e;
        sum += e;
    }
    red[tid] = sum; __syncthreads();
    for (int st = 128; st > 0; st >>= 1) { if (tid < st) red[tid] += red[tid + st]; __syncthreads(); }
    float inv = 1.f / red[0];

    for (int i = tid; i < n; i += 256) {
        float p = rowp[i] * inv;
        bf16 h, l; split2(p, h, l);
        oh[i] = h; ol[i] = l;
    }
    bf16 z = __float2bfloat16(0.f);
    for (int i = n + tid; i < SEQ; i += 256) { oh[i] = z; ol[i] = z; }
}

// ---------------- elementwise ----------------
__global__ void __launch_bounds__(256) add_kernel(float* __restrict__ a, const float* __restrict__ b, int n)
{
    int i = blockIdx.x * 256 + threadIdx.x;
    if (i < n) a[i] += b[i];
}

__global__ void __launch_bounds__(256) silu_mul_split_kernel(
    const float* __restrict__ f, bf16* __restrict__ ghi, bf16* __restrict__ glo, int n)
{
    int i = blockIdx.x * 256 + threadIdx.x;
    if (i < n) {
        int s = i / INTER, c = i - s * INTER;
        long long base = (long long)s * (2 * INTER);
        float x = f[base + c];
        float v = x / (1.f + expf(-x)) * f[base + INTER + c];
        bf16 h, l; split2(v, h, l);
        ghi[i] = h; glo[i] = l;
    }
}

// ---------------- orchestration ----------------
static inline void launch_gemm_w(const bf16* Ahi, const bf16* Alo,
                                 const float* B1, const float* B2, int N1, float* C,
                                 int M, int N, int K, int lda, int ldb, int ldc)
{
    dim3 grid(M / 256, N / 128);
    gemm_wsplit<<<grid, NTW, W_SMEM>>>(Ahi, Alo, B1, B2, N1, C, K, lda, ldb, ldc);
}

static inline void launch_gemm_a(const bf16* Ahi, const bf16* Alo,
                                 const bf16* Bhi, const bf16* Blo, float* C,
                                 int M, int N, int K, int lda, int ldb, int ldc,
                                 long long sA, long long sB, long long sC, int batch, int mode)
{
    dim3 grid(M / 128, N / 128, batch);
    gemm_bf16_split<<<grid, NTA, A_SMEM>>>(Ahi, Alo, Bhi, Blo, C, K, lda, ldb, ldc, sA, sB, sC, mode);
}

extern "C" void kernel_launch(void* const* d_in, const int* in_sizes, int n_in,
                              void* d_out, int out_size)
{
    const float* x      = (const float*)d_in[0];
    const int*   pos    = (const int*)d_in[1];
    const float* qkv_w  = (const float*)d_in[2];
    const float* o_w    = (const float*)d_in[3];
    const float* gate_w = (const float*)d_in[4];
    const float* up_w   = (const float*)d_in[5];
    const float* down_w = (const float*)d_in[6];
    const float* ln1_w  = (const float*)d_in[7];
    const float* ln2_w  = (const float*)d_in[8];
    const float* cosT   = (const float*)d_in[9];
    const float* sinT   = (const float*)d_in[10];
    float* h = (float*)d_out;

    cudaFuncSetAttribute(gemm_wsplit, cudaFuncAttributeMaxDynamicSharedMemorySize, W_SMEM);
    cudaFuncSetAttribute(gemm_bf16_split, cudaFuncAttributeMaxDynamicSharedMemorySize, A_SMEM);
    cudaFuncSetAttribute(rope_v_kernel, cudaFuncAttributeMaxDynamicSharedMemorySize, 128 * 129 * 4);

    float *y, *o, *qkv, *sc, *f;
    bf16 *yhi, *ylo, *qhi, *qlo, *khi, *klo, *vthi, *vtlo, *phi, *plo, *ghi, *glo;
    cudaGetSymbolAddress((void**)&y, g_y);
    cudaGetSymbolAddress((void**)&o, g_o);
    cudaGetSymbolAddress((void**)&qkv, g_qkv);
    cudaGetSymbolAddress((void**)&sc, g_sc);
    cudaGetSymbolAddress((void**)&f, g_f);
    cudaGetSymbolAddress((void**)&yhi, g_yhi);
    cudaGetSymbolAddress((void**)&ylo, g_ylo);
    cudaGetSymbolAddress((void**)&qhi, g_qhi);
    cudaGetSymbolAddress((void**)&qlo, g_qlo);
    cudaGetSymbolAddress((void**)&khi, g_khi);
    cudaGetSymbolAddress((void**)&klo, g_klo);
    cudaGetSymbolAddress((void**)&vthi, g_vthi);
    cudaGetSymbolAddress((void**)&vtlo, g_vtlo);
    cudaGetSymbolAddress((void**)&phi, g_phi);
    cudaGetSymbolAddress((void**)&plo, g_plo);
    cudaGetSymbolAddress((void**)&ghi, g_ghi);
    cudaGetSymbolAddress((void**)&glo, g_glo);

    cudaMemcpyAsync(h, x, sizeof(float) * SEQ * HID, cudaMemcpyDeviceToDevice, 0);

    const int nEl = SEQ * HID;
    const int nElI = SEQ * INTER;
    const int BIGN = 1 << 30;

    rmsnorm_split_kernel<<<SEQ, 256>>>(h, ln1_w, yhi, ylo);

    for (int L = 0; L < NL; L++) {
        const float* qw = qkv_w  + (size_t)L * 3 * HID * HID;
        const float* ow = o_w    + (size_t)L * HID * HID;
        const float* gw = gate_w + (size_t)L * INTER * HID;
        const float* uw = up_w   + (size_t)L * INTER * HID;
        const float* dw = down_w + (size_t)L * HID * INTER;

        // ---- attention ----
        launch_gemm_w(yhi, ylo, qw, qw, BIGN, qkv, SEQ, 3 * HID, HID, HID, HID, 3 * HID);

        rope_v_kernel<<<dim3(NH, SEQ / 128), 256, 128 * 129 * 4>>>(
            qkv, cosT, sinT, pos, qhi, qlo, khi, klo, vthi, vtlo);

        launch_gemm_a(qhi, qlo, khi, klo, sc, SEQ, SEQ, HD, HD, HD, SEQ,
                      (long long)SEQ * HD, (long long)SEQ * HD, (long long)SEQ * SEQ, NH, 1);

        softmax_split_kernel<<<dim3(SEQ, NH), 256>>>(sc, phi, plo);

        launch_gemm_a(phi, plo, vthi, vtlo, y, SEQ, HD, SEQ, SEQ, SEQ, HID,
                      (long long)SEQ * SEQ, (long long)HD * SEQ, (long long)HD, NH, 2);

        { long long n = nEl; split_kernel<<<(int)((n / 4 + 255) / 256), 256>>>(y, yhi, ylo, n); }

        launch_gemm_w(yhi, ylo, ow, ow, BIGN, o, SEQ, HID, HID, HID, HID, HID);

        add_rms_split_kernel<<<SEQ, 256>>>(h, o, ln2_w + (size_t)L * HID, yhi, ylo);

        // ---- MLP: fused gate|up ----
        launch_gemm_w(yhi, ylo, gw, uw, INTER, f, SEQ, 2 * INTER, HID, HID, HID, 2 * INTER);

        silu_mul_split_kernel<<<nElI / 256, 256>>>(f, ghi, glo, nElI);

        launch_gemm_w(ghi, glo, dw, dw, BIGN, o, SEQ, HID, INTER, INTER, INTER, HID);

        if (L < NL - 1) {
            add_rms_split_kernel<<<SEQ, 256>>>(h, o, ln1_w + (size_t)(L + 1) * HID, yhi, ylo);
        } else {
            add_kernel<<<nEl / 256, 256>>>(h, o, nEl);
        }
    }
}

// round 16
// speedup vs baseline: 1.2072x; 1.1530x over previous
#include <cuda_runtime.h>
#include <cuda_bf16.h>
#include <math.h>
#include <stdint.h>

#define SEQ   1024
#define HID   4096
#define NH    32
#define HD    128
#define INTER 11008
#define NL    2

typedef __nv_bfloat16 bf16;

// ---------------- scratch (device globals; no allocations allowed) ----------
__device__ float g_y[SEQ * HID];
__device__ float g_o[SEQ * HID];
__device__ float g_qkv[SEQ * 3 * HID];
__device__ float g_sc[(size_t)NH * SEQ * SEQ];
__device__ float g_f[(size_t)SEQ * 2 * INTER];

__device__ bf16 g_yhi[SEQ * HID],  g_ylo[SEQ * HID];
__device__ bf16 g_qhi[SEQ * HID],  g_qlo[SEQ * HID];
__device__ bf16 g_khi[SEQ * HID],  g_klo[SEQ * HID];
__device__ bf16 g_vthi[SEQ * HID], g_vtlo[SEQ * HID];
__device__ bf16 g_phi[(size_t)NH * SEQ * SEQ], g_plo[(size_t)NH * SEQ * SEQ];
__device__ bf16 g_ghi[SEQ * INTER], g_glo[SEQ * INTER];

// ======================= helpers ==============================
__device__ __forceinline__ uint32_t smem_u32(const void* p) {
    uint32_t a;
    asm("{ .reg .u64 t; cvta.to.shared.u64 t, %1; cvt.u32.u64 %0, t; }" : "=r"(a) : "l"(p));
    return a;
}

__device__ __forceinline__ void ldsm_x4(uint32_t* r, uint32_t addr) {
    asm volatile("ldmatrix.sync.aligned.m8n8.x4.shared.b16 {%0,%1,%2,%3}, [%4];"
                 : "=r"(r[0]), "=r"(r[1]), "=r"(r[2]), "=r"(r[3]) : "r"(addr));
}

__device__ __forceinline__ void mma_bf16(float* c, const uint32_t* a, uint32_t b0, uint32_t b1) {
    asm volatile(
        "mma.sync.aligned.m16n8k16.row.col.f32.bf16.bf16.f32 "
        "{%0,%1,%2,%3}, {%4,%5,%6,%7}, {%8,%9}, {%0,%1,%2,%3};"
        : "+f"(c[0]), "+f"(c[1]), "+f"(c[2]), "+f"(c[3])
        : "r"(a[0]), "r"(a[1]), "r"(a[2]), "r"(a[3]), "r"(b0), "r"(b1));
}

#define CP16(dst, src) asm volatile("cp.async.cg.shared.global [%0], [%1], 16;" :: "r"(dst), "l"(src))
#define CP_COMMIT()    asm volatile("cp.async.commit_group;" ::: "memory")
#define CP_WAIT1()     asm volatile("cp.async.wait_group 1;" ::: "memory")
#define CP_WAIT0()     asm volatile("cp.async.wait_group 0;" ::: "memory")

__device__ __forceinline__ void split2(float x, bf16& h, bf16& l) {
    h = __float2bfloat16(x);
    l = __float2bfloat16(x - __bfloat162float(h));
}

__device__ __forceinline__ uint32_t pk(bf16 a, bf16 b) {
    return (uint32_t)__bfloat16_as_ushort(a) | ((uint32_t)__bfloat16_as_ushort(b) << 16);
}

#define ROWB 80

// term-major MMA block for one mt: 4x hh, 4x lh, 4x hl
#define MMA_TERM_MAJOR(accmt, ah, al, bh, bl)                                   \
    do {                                                                        \
        _Pragma("unroll")                                                       \
        for (int nt = 0; nt < 4; nt++)                                          \
            mma_bf16((accmt)[nt], ah, bh[nt >> 1][(nt & 1) * 2],                \
                     bh[nt >> 1][(nt & 1) * 2 + 1]);                            \
        _Pragma("unroll")                                                       \
        for (int nt = 0; nt < 4; nt++)                                          \
            mma_bf16((accmt)[nt], al, bh[nt >> 1][(nt & 1) * 2],                \
                     bh[nt >> 1][(nt & 1) * 2 + 1]);                            \
        _Pragma("unroll")                                                       \
        for (int nt = 0; nt < 4; nt++)                                          \
            mma_bf16((accmt)[nt], ah, bl[nt >> 1][(nt & 1) * 2],                \
                     bl[nt >> 1][(nt & 1) * 2 + 1]);                            \
    } while (0)

// =================== WEIGHT GEMM (round-12 winner): 256x128, 512 thr, 3-stage
#define NTW    512
#define W_ATILE  (256 * ROWB)                 // 20480 B
#define W_BTILE  (128 * ROWB)                 // 10240 B
#define W_STAGEB (2 * W_ATILE + 2 * W_BTILE)  // 61440 B
#define W_STAGES 3
#define W_SMEM   (W_STAGES * W_STAGEB)        // 184320 B

__device__ __forceinline__ void w_a_stage_load(
    uint32_t sdst, const bf16* __restrict__ Ahi, const bf16* __restrict__ Alo,
    int lda, int k0, int bm, int tid)
{
    #pragma unroll
    for (int i = 0; i < 2; i++) {
        int idx = tid + i * NTW;
        int r = idx >> 2, seg = (idx & 3) * 8;
        uint32_t so = sdst + (uint32_t)r * ROWB + (uint32_t)seg * 2;
        long long g = (long long)(bm + r) * lda + k0 + seg;
        CP16(so,           Ahi + g);
        CP16(so + W_ATILE, Alo + g);
    }
}

__global__ void __launch_bounds__(NTW, 1)
gemm_wsplit(const bf16* __restrict__ Ahi, const bf16* __restrict__ Alo,
            const float* __restrict__ B1, const float* __restrict__ B2, int N1,
            float* __restrict__ C, int K, int lda, int ldb, int ldc)
{
    extern __shared__ char smem[];
    const int tid = threadIdx.x;
    const int lane = tid & 31;
    const int wid = tid >> 5;
    const int wm = wid & 3;           // 0..3 (64-row quadrant)
    const int wn = wid >> 2;          // 0..3 (32-col quarter)

    const int bm = blockIdx.x * 256;
    const int bn = blockIdx.y * 128;

    const float* W = (bn < N1) ? (B1 + (long long)bn * ldb)
                               : (B2 + (long long)(bn - N1) * ldb);

    const uint32_t sb = smem_u32(smem);
    const int nk = K / 32;

    // B loader: 4 threads per row, 8 fp32 each
    const int br = tid >> 2;
    const int bc = (tid & 3) * 8;
    const float* Wrow = W + (long long)br * ldb + bc;
    const uint32_t bsts = (uint32_t)br * ROWB + (uint32_t)bc * 2;

    const uint32_t aOff = (uint32_t)(wm * 64 + (lane & 15)) * ROWB + (uint32_t)(lane >> 4) * 16;
    const uint32_t bOff = (uint32_t)(wn * 32 + (((lane >> 4) << 3) | (lane & 7))) * ROWB
                        + (uint32_t)((lane >> 3) & 1) * 16;

    float acc[4][4][4];
    #pragma unroll
    for (int mt = 0; mt < 4; mt++)
        #pragma unroll
        for (int nt = 0; nt < 4; nt++)
            #pragma unroll
            for (int i = 0; i < 4; i++) acc[mt][nt][i] = 0.f;

    float4 rB[2];

    // ---- prologue ----
    rB[0] = *reinterpret_cast<const float4*>(Wrow);
    rB[1] = *reinterpret_cast<const float4*>(Wrow + 4);
    {
        bf16 h0,h1,h2,h3,l0,l1,l2,l3;
        #pragma unroll
        for (int v = 0; v < 2; v++) {
            split2(rB[v].x, h0, l0); split2(rB[v].y, h1, l1);
            split2(rB[v].z, h2, l2); split2(rB[v].w, h3, l3);
            *reinterpret_cast<uint2*>(smem + 2 * W_ATILE + bsts + v * 8) = make_uint2(pk(h0,h1), pk(h2,h3));
            *reinterpret_cast<uint2*>(smem + 2 * W_ATILE + W_BTILE + bsts + v * 8) = make_uint2(pk(l0,l1), pk(l2,l3));
        }
    }
    w_a_stage_load(sb, Ahi, Alo, lda, 0, bm, tid);
    CP_COMMIT();
    if (nk > 1) w_a_stage_load(sb + W_STAGEB, Ahi, Alo, lda, 32, bm, tid);
    CP_COMMIT();
    if (nk > 1) {
        rB[0] = *reinterpret_cast<const float4*>(Wrow + 32);
        rB[1] = *reinterpret_cast<const float4*>(Wrow + 36);
    }

    for (int j = 0; j < nk; j++) {
        CP_WAIT1();
        __syncthreads();

        int jn = j + 2;
        if (jn < nk)
            w_a_stage_load(sb + (uint32_t)(jn % W_STAGES) * W_STAGEB, Ahi, Alo, lda, jn * 32, bm, tid);
        CP_COMMIT();

        const uint32_t st = sb + (uint32_t)(j % W_STAGES) * W_STAGEB;
        #pragma unroll
        for (int kk = 0; kk < 2; kk++) {
            uint32_t bh[2][4], bl[2][4];
            #pragma unroll
            for (int n2 = 0; n2 < 2; n2++) {
                uint32_t base = st + bOff + 2 * W_ATILE + (uint32_t)n2 * (16 * ROWB) + (uint32_t)kk * 32;
                ldsm_x4(bh[n2], base);
                ldsm_x4(bl[n2], base + W_BTILE);
            }
            #pragma unroll
            for (int mt = 0; mt < 4; mt++) {
                uint32_t ah[4], al[4];
                uint32_t base = st + aOff + (uint32_t)mt * (16 * ROWB) + (uint32_t)kk * 32;
                ldsm_x4(ah, base);
                ldsm_x4(al, base + W_ATILE);
                MMA_TERM_MAJOR(acc[mt], ah, al, bh, bl);
            }
        }

        if (j + 1 < nk) {
            uint32_t dst = (uint32_t)((j + 1) % W_STAGES) * W_STAGEB + 2 * W_ATILE + bsts;
            bf16 h0,h1,h2,h3,l0,l1,l2,l3;
            #pragma unroll
            for (int v = 0; v < 2; v++) {
                split2(rB[v].x, h0, l0); split2(rB[v].y, h1, l1);
                split2(rB[v].z, h2, l2); split2(rB[v].w, h3, l3);
                *reinterpret_cast<uint2*>(smem + dst + v * 8) = make_uint2(pk(h0,h1), pk(h2,h3));
                *reinterpret_cast<uint2*>(smem + dst + W_BTILE + v * 8) = make_uint2(pk(l0,l1), pk(l2,l3));
            }
        }
        if (j + 2 < nk) {
            const float* p = Wrow + (j + 2) * 32;
            rB[0] = *reinterpret_cast<const float4*>(p);
            rB[1] = *reinterpret_cast<const float4*>(p + 4);
        }
    }

    const int gr = lane >> 2;
    const int gc = (lane & 3) * 2;
    #pragma unroll
    for (int mt = 0; mt < 4; mt++) {
        int row0 = bm + wm * 64 + mt * 16 + gr;
        #pragma unroll
        for (int nt = 0; nt < 4; nt++) {
            int c = bn + wn * 32 + nt * 8 + gc;
            *reinterpret_cast<float2*>(C + (long long)row0 * ldc + c) =
                make_float2(acc[mt][nt][0], acc[mt][nt][1]);
            *reinterpret_cast<float2*>(C + (long long)(row0 + 8) * ldc + c) =
                make_float2(acc[mt][nt][2], acc[mt][nt][3]);
        }
    }
}

// === ATTENTION GEMM (round-15 winner): 128x128, 256 thr, 2-stage, 2 CTAs/SM,
//     single sync per chunk =================================================
#define NTA    256
#define A_ATILE  (128 * ROWB)
#define A_BTILE  (128 * ROWB)
#define A_STAGEB (2 * A_ATILE + 2 * A_BTILE)  // 40960
#define A_SMEM   (2 * A_STAGEB)               // 81920

__device__ __forceinline__ void stage_load_ab(
    uint32_t sdst,
    const bf16* __restrict__ Ahi, const bf16* __restrict__ Alo,
    const bf16* __restrict__ Bhi, const bf16* __restrict__ Blo,
    int lda, int ldb, int k0, int bm, int bn, int tid)
{
    #pragma unroll
    for (int i = 0; i < 2; i++) {
        int idx = tid + i * NTA;
        int r = idx >> 2, seg = (idx & 3) * 8;
        uint32_t soA = sdst + (uint32_t)r * ROWB + (uint32_t)seg * 2;
        long long gA = (long long)(bm + r) * lda + k0 + seg;
        CP16(soA,           Ahi + gA);
        CP16(soA + A_ATILE, Alo + gA);
        uint32_t soB = sdst + 2 * A_ATILE + (uint32_t)r * ROWB + (uint32_t)seg * 2;
        long long gB = (long long)(bn + r) * ldb + k0 + seg;
        CP16(soB,           Bhi + gB);
        CP16(soB + A_BTILE, Blo + gB);
    }
}

__global__ void __launch_bounds__(NTA, 2)
gemm_bf16_split(const bf16* __restrict__ Ahi, const bf16* __restrict__ Alo,
                const bf16* __restrict__ Bhi, const bf16* __restrict__ Blo,
                float* __restrict__ C, int K, int lda, int ldb, int ldc,
                long long sA, long long sB, long long sC, int mode)
{
    extern __shared__ char smem[];
    const int tid = threadIdx.x;
    const int lane = tid & 31;
    const int wid = tid >> 5;
    const int wm = wid & 1;
    const int wn = wid >> 1;

    const int bm = blockIdx.x * 128;
    const int bn = blockIdx.y * 128;
    if (mode == 1 && bn >= bm + 128) return;

    Ahi += (long long)blockIdx.z * sA;
    Alo += (long long)blockIdx.z * sA;
    Bhi += (long long)blockIdx.z * sB;
    Blo += (long long)blockIdx.z * sB;
    C   += (long long)blockIdx.z * sC;

    int kend = (mode == 2) ? min(K, bm + 128) : K;
    const int nk = kend / 32;

    const uint32_t sb = smem_u32(smem);

    const uint32_t aOff = (uint32_t)(wm * 64 + (lane & 15)) * ROWB + (uint32_t)(lane >> 4) * 16;
    const uint32_t bOff = (uint32_t)(wn * 32 + (((lane >> 4) << 3) | (lane & 7))) * ROWB
                        + (uint32_t)((lane >> 3) & 1) * 16;

    float acc[4][4][4];
    #pragma unroll
    for (int mt = 0; mt < 4; mt++)
        #pragma unroll
        for (int nt = 0; nt < 4; nt++)
            #pragma unroll
            for (int i = 0; i < 4; i++) acc[mt][nt][i] = 0.f;

    stage_load_ab(sb, Ahi, Alo, Bhi, Blo, lda, ldb, 0, bm, bn, tid);
    CP_COMMIT();

    for (int j = 0; j < nk; j++) {
        CP_WAIT0();
        __syncthreads();

        if (j + 1 < nk) {
            stage_load_ab(sb + (uint32_t)((j + 1) & 1) * A_STAGEB,
                          Ahi, Alo, Bhi, Blo, lda, ldb, (j + 1) * 32, bm, bn, tid);
            CP_COMMIT();
        }

        const uint32_t st = sb + (uint32_t)(j & 1) * A_STAGEB;
        #pragma unroll
        for (int kk = 0; kk < 2; kk++) {
            uint32_t bh[2][4], bl[2][4];
            #pragma unroll
            for (int n2 = 0; n2 < 2; n2++) {
                uint32_t base = st + bOff + 2 * A_ATILE + (uint32_t)n2 * (16 * ROWB) + (uint32_t)kk * 32;
                ldsm_x4(bh[n2], base);
                ldsm_x4(bl[n2], base + A_BTILE);
            }
            #pragma unroll
            for (int mt = 0; mt < 4; mt++) {
                uint32_t ah[4], al[4];
                uint32_t base = st + aOff + (uint32_t)mt * (16 * ROWB) + (uint32_t)kk * 32;
                ldsm_x4(ah, base);
                ldsm_x4(al, base + A_ATILE);
                MMA_TERM_MAJOR(acc[mt], ah, al, bh, bl);
            }
        }
    }

    const int gr = lane >> 2;
    const int gc = (lane & 3) * 2;
    #pragma unroll
    for (int mt = 0; mt < 4; mt++) {
        int row0 = bm + wm * 64 + mt * 16 + gr;
        #pragma unroll
        for (int nt = 0; nt < 4; nt++) {
            int c = bn + wn * 32 + nt * 8 + gc;
            *reinterpret_cast<float2*>(C + (long long)row0 * ldc + c) =
                make_float2(acc[mt][nt][0], acc[mt][nt][1]);
            *reinterpret_cast<float2*>(C + (long long)(row0 + 8) * ldc + c) =
                make_float2(acc[mt][nt][2], acc[mt][nt][3]);
        }
    }
}

// ---------------- fp32 -> bf16 hi/lo split ----------------
__global__ void __launch_bounds__(256) split_kernel(
    const float* __restrict__ in, bf16* __restrict__ hi, bf16* __restrict__ lo, long long n)
{
    long long i = ((long long)blockIdx.x * 256 + threadIdx.x) * 4;
    if (i >= n) return;
    float4 v = *reinterpret_cast<const float4*>(in + i);
    bf16 h0, h1, h2, h3, l0, l1, l2, l3;
    split2(v.x, h0, l0); split2(v.y, h1, l1); split2(v.z, h2, l2); split2(v.w, h3, l3);
    *reinterpret_cast<uint2*>(hi + i) = make_uint2(pk(h0,h1), pk(h2,h3));
    *reinterpret_cast<uint2*>(lo + i) = make_uint2(pk(l0,l1), pk(l2,l3));
}

// ---------------- RMSNorm with fused split ----------------
__global__ void __launch_bounds__(256) rmsnorm_split_kernel(
    const float* __restrict__ x, const float* __restrict__ w,
    bf16* __restrict__ yhi, bf16* __restrict__ ylo)
{
    int s = blockIdx.x;
    const float* rowp = x + (long long)s * HID;
    int tid = threadIdx.x;

    float ss = 0.f;
    for (int i = tid; i < HID; i += 256) { float v = rowp[i]; ss += v * v; }
    __shared__ float red[256];
    red[tid] = ss; __syncthreads();
    for (int st = 128; st > 0; st >>= 1) { if (tid < st) red[tid] += red[tid + st]; __syncthreads(); }
    float inv = rsqrtf(red[0] / (float)HID + 1e-6f);

    bf16* oh = yhi + (long long)s * HID;
    bf16* ol = ylo + (long long)s * HID;
    for (int i = tid; i < HID; i += 256) {
        float v = rowp[i] * inv * w[i];
        bf16 h, l; split2(v, h, l);
        oh[i] = h; ol[i] = l;
    }
}

// ------------ fused residual add + RMSNorm + split ----------------
__global__ void __launch_bounds__(256) add_rms_split_kernel(
    float* __restrict__ h, const float* __restrict__ o, const float* __restrict__ w,
    bf16* __restrict__ yhi, bf16* __restrict__ ylo)
{
    int s = blockIdx.x;
    long long base = (long long)s * HID;
    int tid = threadIdx.x;
    __shared__ float v[HID];
    __shared__ float red[256];

    float ss = 0.f;
    for (int i = tid; i < HID; i += 256) {
        float t = h[base + i] + o[base + i];
        h[base + i] = t;
        v[i] = t;
        ss += t * t;
    }
    red[tid] = ss; __syncthreads();
    for (int st = 128; st > 0; st >>= 1) { if (tid < st) red[tid] += red[tid + st]; __syncthreads(); }
    float inv = rsqrtf(red[0] / (float)HID + 1e-6f);

    bf16* oh = yhi + base;
    bf16* ol = ylo + base;
    for (int i = tid; i < HID; i += 256) {
        float t = v[i] * inv * w[i];
        bf16 hh, ll; split2(t, hh, ll);
        oh[i] = hh; ol[i] = ll;
    }
}

// -------- RoPE q/k + coalesced V transpose ----------------
__global__ void __launch_bounds__(256) rope_v_kernel(
    const float* __restrict__ qkv,
    const float* __restrict__ cosT, const float* __restrict__ sinT,
    const int* __restrict__ pos_ids,
    bf16* __restrict__ qhi, bf16* __restrict__ qlo,
    bf16* __restrict__ khi, bf16* __restrict__ klo,
    bf16* __restrict__ vthi, bf16* __restrict__ vtlo)
{
    extern __shared__ uint32_t T[];
    int head = blockIdx.x;
    int st = blockIdx.y * 128;
    int tid = threadIdx.x;

    for (int i = tid; i < 128 * 128; i += 256) {
        int sl = i >> 7, d = i & 127;
        int s = st + sl;
        int pos = pos_ids[s];
        if (pos < 0) pos = 0;
        if (pos >= SEQ) pos = SEQ - 1;
        const float* rowp = qkv + (long long)s * (3 * HID);
        int idx = head * HD + d;
        float qv = rowp[idx];
        float kv = rowp[HID + idx];
        float vv = rowp[2 * HID + idx];
        float qo = (d < 64) ? -rowp[idx + 64] : rowp[idx - 64];
        float ko = (d < 64) ? -rowp[HID + idx + 64] : rowp[HID + idx - 64];
        float cd = cosT[(long long)pos * HD + d];
        float sd = sinT[(long long)pos * HD + d];
        float qr = qv * cd + qo * sd;
        float kr = kv * cd + ko * sd;
        long long qi = ((long long)head * SEQ + s) * HD + d;
        bf16 hh, ll;
        split2(qr, hh, ll); qhi[qi] = hh; qlo[qi] = ll;
        split2(kr, hh, ll); khi[qi] = hh; klo[qi] = ll;
        split2(vv, hh, ll);
        T[sl * 129 + d] = pk(hh, ll);
    }
    __syncthreads();
    for (int i = tid; i < 128 * 128; i += 256) {
        int d = i >> 7, sl = i & 127;
        uint32_t p = T[sl * 129 + d];
        long long vi = ((long long)head * HD + d) * SEQ + st + sl;
        vthi[vi] = __ushort_as_bfloat16((unsigned short)(p & 0xFFFF));
        vtlo[vi] = __ushort_as_bfloat16((unsigned short)(p >> 16));
    }
}

// ---------------- causal softmax with fused split ----------------
__global__ void __launch_bounds__(256) softmax_split_kernel(
    float* __restrict__ scores, bf16* __restrict__ phi, bf16* __restrict__ plo)
{
    int qrow = blockIdx.x;
    int head = blockIdx.y;
    long long off = ((long long)head * SEQ + qrow) * SEQ;
    float* rowp = scores + off;
    bf16* oh = phi + off;
    bf16* ol = plo + off;
    int n = qrow + 1;
    int tid = threadIdx.x;
    const float scale = 0.088388347648318447f;

    __shared__ float red[256];

    float m = -3.4e38f;
    for (int i = tid; i < n; i += 256) m = fmaxf(m, rowp[i] * scale);
    red[tid] = m; __syncthreads();
    for (int st = 128; st > 0; st >>= 1) { if (tid < st) red[tid] = fmaxf(red[tid], red[tid + st]); __syncthreads(); }
    m = red[0]; __syncthreads();

    float sum = 0.f;
    for (int i = tid; i < n; i += 256) {
        float e = expf(rowp[i] * scale - m);
        rowp[i] = e;
        sum += e;
    }
    red[tid] = sum; __syncthreads();
    for (int st = 128; st > 0; st >>= 1) { if (tid < st) red[tid] += red[tid + st]; __syncthreads(); }
    float inv = 1.f / red[0];

    for (int i = tid; i < n; i += 256) {
        float p = rowp[i] * inv;
        bf16 h, l; split2(p, h, l);
        oh[i] = h; ol[i] = l;
    }
    bf16 z = __float2bfloat16(0.f);
    for (int i = n + tid; i < SEQ; i += 256) { oh[i] = z; ol[i] = z; }
}

// ---------------- elementwise ----------------
__global__ void __launch_bounds__(256) add_kernel(float* __restrict__ a, const float* __restrict__ b, int n)
{
    int i = blockIdx.x * 256 + threadIdx.x;
    if (i < n) a[i] += b[i];
}

__global__ void __launch_bounds__(256) silu_mul_split_kernel(
    const float* __restrict__ f, bf16* __restrict__ ghi, bf16* __restrict__ glo, int n)
{
    int i = blockIdx.x * 256 + threadIdx.x;
    if (i < n) {
        int s = i / INTER, c = i - s * INTER;
        long long base = (long long)s * (2 * INTER);
        float x = f[base + c];
        float v = x / (1.f + expf(-x)) * f[base + INTER + c];
        bf16 h, l; split2(v, h, l);
        ghi[i] = h; glo[i] = l;
    }
}

// ---------------- orchestration ----------------
static inline void launch_gemm_w(const bf16* Ahi, const bf16* Alo,
                                 const float* B1, const float* B2, int N1, float* C,
                                 int M, int N, int K, int lda, int ldb, int ldc)
{
    dim3 grid(M / 256, N / 128);
    gemm_wsplit<<<grid, NTW, W_SMEM>>>(Ahi, Alo, B1, B2, N1, C, K, lda, ldb, ldc);
}

static inline void launch_gemm_a(const bf16* Ahi, const bf16* Alo,
                                 const bf16* Bhi, const bf16* Blo, float* C,
                                 int M, int N, int K, int lda, int ldb, int ldc,
                                 long long sA, long long sB, long long sC, int batch, int mode)
{
    dim3 grid(M / 128, N / 128, batch);
    gemm_bf16_split<<<grid, NTA, A_SMEM>>>(Ahi, Alo, Bhi, Blo, C, K, lda, ldb, ldc, sA, sB, sC, mode);
}

extern "C" void kernel_launch(void* const* d_in, const int* in_sizes, int n_in,
                              void* d_out, int out_size)
{
    const float* x      = (const float*)d_in[0];
    const int*   pos    = (const int*)d_in[1];
    const float* qkv_w  = (const float*)d_in[2];
    const float* o_w    = (const float*)d_in[3];
    const float* gate_w = (const float*)d_in[4];
    const float* up_w   = (const float*)d_in[5];
    const float* down_w = (const float*)d_in[6];
    const float* ln1_w  = (const float*)d_in[7];
    const float* ln2_w  = (const float*)d_in[8];
    const float* cosT   = (const float*)d_in[9];
    const float* sinT   = (const float*)d_in[10];
    float* h = (float*)d_out;

    cudaFuncSetAttribute(gemm_wsplit, cudaFuncAttributeMaxDynamicSharedMemorySize, W_SMEM);
    cudaFuncSetAttribute(gemm_bf16_split, cudaFuncAttributeMaxDynamicSharedMemorySize, A_SMEM);
    cudaFuncSetAttribute(rope_v_kernel, cudaFuncAttributeMaxDynamicSharedMemorySize, 128 * 129 * 4);

    float *y, *o, *qkv, *sc, *f;
    bf16 *yhi, *ylo, *qhi, *qlo, *khi, *klo, *vthi, *vtlo, *phi, *plo, *ghi, *glo;
    cudaGetSymbolAddress((void**)&y, g_y);
    cudaGetSymbolAddress((void**)&o, g_o);
    cudaGetSymbolAddress((void**)&qkv, g_qkv);
    cudaGetSymbolAddress((void**)&sc, g_sc);
    cudaGetSymbolAddress((void**)&f, g_f);
    cudaGetSymbolAddress((void**)&yhi, g_yhi);
    cudaGetSymbolAddress((void**)&ylo, g_ylo);
    cudaGetSymbolAddress((void**)&qhi, g_qhi);
    cudaGetSymbolAddress((void**)&qlo, g_qlo);
    cudaGetSymbolAddress((void**)&khi, g_khi);
    cudaGetSymbolAddress((void**)&klo, g_klo);
    cudaGetSymbolAddress((void**)&vthi, g_vthi);
    cudaGetSymbolAddress((void**)&vtlo, g_vtlo);
    cudaGetSymbolAddress((void**)&phi, g_phi);
    cudaGetSymbolAddress((void**)&plo, g_plo);
    cudaGetSymbolAddress((void**)&ghi, g_ghi);
    cudaGetSymbolAddress((void**)&glo, g_glo);

    cudaMemcpyAsync(h, x, sizeof(float) * SEQ * HID, cudaMemcpyDeviceToDevice, 0);

    const int nEl = SEQ * HID;
    const int nElI = SEQ * INTER;
    const int BIGN = 1 << 30;

    rmsnorm_split_kernel<<<SEQ, 256>>>(h, ln1_w, yhi, ylo);

    for (int L = 0; L < NL; L++) {
        const float* qw = qkv_w  + (size_t)L * 3 * HID * HID;
        const float* ow = o_w    + (size_t)L * HID * HID;
        const float* gw = gate_w + (size_t)L * INTER * HID;
        const float* uw = up_w   + (size_t)L * INTER * HID;
        const float* dw = down_w + (size_t)L * HID * INTER;

        // ---- attention ----
        launch_gemm_w(yhi, ylo, qw, qw, BIGN, qkv, SEQ, 3 * HID, HID, HID, HID, 3 * HID);

        rope_v_kernel<<<dim3(NH, SEQ / 128), 256, 128 * 129 * 4>>>(
            qkv, cosT, sinT, pos, qhi, qlo, khi, klo, vthi, vtlo);

        launch_gemm_a(qhi, qlo, khi, klo, sc, SEQ, SEQ, HD, HD, HD, SEQ,
                      (long long)SEQ * HD, (long long)SEQ * HD, (long long)SEQ * SEQ, NH, 1);

        softmax_split_kernel<<<dim3(SEQ, NH), 256>>>(sc, phi, plo);

        launch_gemm_a(phi, plo, vthi, vtlo, y, SEQ, HD, SEQ, SEQ, SEQ, HID,
                      (long long)SEQ * SEQ, (long long)HD * SEQ, (long long)HD, NH, 2);

        { long long n = nEl; split_kernel<<<(int)((n / 4 + 255) / 256), 256>>>(y, yhi, ylo, n); }

        launch_gemm_w(yhi, ylo, ow, ow, BIGN, o, SEQ, HID, HID, HID, HID, HID);

        add_rms_split_kernel<<<SEQ, 256>>>(h, o, ln2_w + (size_t)L * HID, yhi, ylo);

        // ---- MLP: fused gate|up ----
        launch_gemm_w(yhi, ylo, gw, uw, INTER, f, SEQ, 2 * INTER, HID, HID, HID, 2 * INTER);

        silu_mul_split_kernel<<<nElI / 256, 256>>>(f, ghi, glo, nElI);

        launch_gemm_w(ghi, glo, dw, dw, BIGN, o, SEQ, HID, INTER, INTER, INTER, HID);

        if (L < NL - 1) {
            add_rms_split_kernel<<<SEQ, 256>>>(h, o, ln1_w + (size_t)(L + 1) * HID, yhi, ylo);
        } else {
            add_kernel<<<nEl / 256, 256>>>(h, o, nEl);
        }
    }
}

// round 17
// speedup vs baseline: 1.2073x; 1.0001x over previous
#include <cuda_runtime.h>
#include <cuda_bf16.h>
#include <math.h>
#include <stdint.h>

#define SEQ   1024
#define HID   4096
#define NH    32
#define HD    128
#define INTER 11008
#define NL    2

typedef __nv_bfloat16 bf16;

// ---------------- scratch (device globals; no allocations allowed) ----------
__device__ float g_o[SEQ * HID];
__device__ float g_qkv[SEQ * 3 * HID];
__device__ float g_sc[(size_t)NH * SEQ * SEQ];
__device__ float g_f[(size_t)SEQ * 2 * INTER];

__device__ bf16 g_yhi[SEQ * HID],  g_ylo[SEQ * HID];
__device__ bf16 g_qhi[SEQ * HID],  g_qlo[SEQ * HID];
__device__ bf16 g_khi[SEQ * HID],  g_klo[SEQ * HID];
__device__ bf16 g_vthi[SEQ * HID], g_vtlo[SEQ * HID];
__device__ bf16 g_phi[(size_t)NH * SEQ * SEQ], g_plo[(size_t)NH * SEQ * SEQ];
__device__ bf16 g_ghi[SEQ * INTER], g_glo[SEQ * INTER];

// ======================= helpers ==============================
__device__ __forceinline__ uint32_t smem_u32(const void* p) {
    uint32_t a;
    asm("{ .reg .u64 t; cvta.to.shared.u64 t, %1; cvt.u32.u64 %0, t; }" : "=r"(a) : "l"(p));
    return a;
}

__device__ __forceinline__ void ldsm_x4(uint32_t* r, uint32_t addr) {
    asm volatile("ldmatrix.sync.aligned.m8n8.x4.shared.b16 {%0,%1,%2,%3}, [%4];"
                 : "=r"(r[0]), "=r"(r[1]), "=r"(r[2]), "=r"(r[3]) : "r"(addr));
}

__device__ __forceinline__ void mma_bf16(float* c, const uint32_t* a, uint32_t b0, uint32_t b1) {
    asm volatile(
        "mma.sync.aligned.m16n8k16.row.col.f32.bf16.bf16.f32 "
        "{%0,%1,%2,%3}, {%4,%5,%6,%7}, {%8,%9}, {%0,%1,%2,%3};"
        : "+f"(c[0]), "+f"(c[1]), "+f"(c[2]), "+f"(c[3])
        : "r"(a[0]), "r"(a[1]), "r"(a[2]), "r"(a[3]), "r"(b0), "r"(b1));
}

#define CP16(dst, src) asm volatile("cp.async.cg.shared.global [%0], [%1], 16;" :: "r"(dst), "l"(src))
#define CP_COMMIT()    asm volatile("cp.async.commit_group;" ::: "memory")
#define CP_WAIT1()     asm volatile("cp.async.wait_group 1;" ::: "memory")
#define CP_WAIT0()     asm volatile("cp.async.wait_group 0;" ::: "memory")

__device__ __forceinline__ void split2(float x, bf16& h, bf16& l) {
    h = __float2bfloat16(x);
    l = __float2bfloat16(x - __bfloat162float(h));
}

__device__ __forceinline__ uint32_t pk(bf16 a, bf16 b) {
    return (uint32_t)__bfloat16_as_ushort(a) | ((uint32_t)__bfloat16_as_ushort(b) << 16);
}

#define ROWB 80

// term-major MMA block for one mt: 4x hh, 4x lh, 4x hl
#define MMA_TERM_MAJOR(accmt, ah, al, bh, bl)                                   \
    do {                                                                        \
        _Pragma("unroll")                                                       \
        for (int nt = 0; nt < 4; nt++)                                          \
            mma_bf16((accmt)[nt], ah, bh[nt >> 1][(nt & 1) * 2],                \
                     bh[nt >> 1][(nt & 1) * 2 + 1]);                            \
        _Pragma("unroll")                                                       \
        for (int nt = 0; nt < 4; nt++)                                          \
            mma_bf16((accmt)[nt], al, bh[nt >> 1][(nt & 1) * 2],                \
                     bh[nt >> 1][(nt & 1) * 2 + 1]);                            \
        _Pragma("unroll")                                                       \
        for (int nt = 0; nt < 4; nt++)                                          \
            mma_bf16((accmt)[nt], ah, bl[nt >> 1][(nt & 1) * 2],                \
                     bl[nt >> 1][(nt & 1) * 2 + 1]);                            \
    } while (0)

// =================== WEIGHT GEMM: 256x128, 512 thr, 3-stage, 1 CTA/SM =======
#define NTW    512
#define W_ATILE  (256 * ROWB)
#define W_BTILE  (128 * ROWB)
#define W_STAGEB (2 * W_ATILE + 2 * W_BTILE)
#define W_STAGES 3
#define W_SMEM   (W_STAGES * W_STAGEB)        // 184320 B

__device__ __forceinline__ void w_a_stage_load(
    uint32_t sdst, const bf16* __restrict__ Ahi, const bf16* __restrict__ Alo,
    int lda, int k0, int bm, int tid)
{
    #pragma unroll
    for (int i = 0; i < 2; i++) {
        int idx = tid + i * NTW;
        int r = idx >> 2, seg = (idx & 3) * 8;
        uint32_t so = sdst + (uint32_t)r * ROWB + (uint32_t)seg * 2;
        long long g = (long long)(bm + r) * lda + k0 + seg;
        CP16(so,           Ahi + g);
        CP16(so + W_ATILE, Alo + g);
    }
}

__global__ void __launch_bounds__(NTW, 1)
gemm_wsplit(const bf16* __restrict__ Ahi, const bf16* __restrict__ Alo,
            const float* __restrict__ B1, const float* __restrict__ B2, int N1,
            float* __restrict__ C, int K, int lda, int ldb, int ldc)
{
    extern __shared__ char smem[];
    const int tid = threadIdx.x;
    const int lane = tid & 31;
    const int wid = tid >> 5;
    const int wm = wid & 3;
    const int wn = wid >> 2;

    const int bm = blockIdx.x * 256;
    const int bn = blockIdx.y * 128;

    const float* W = (bn < N1) ? (B1 + (long long)bn * ldb)
                               : (B2 + (long long)(bn - N1) * ldb);

    const uint32_t sb = smem_u32(smem);
    const int nk = K / 32;

    const int br = tid >> 2;
    const int bc = (tid & 3) * 8;
    const float* Wrow = W + (long long)br * ldb + bc;
    const uint32_t bsts = (uint32_t)br * ROWB + (uint32_t)bc * 2;

    const uint32_t aOff = (uint32_t)(wm * 64 + (lane & 15)) * ROWB + (uint32_t)(lane >> 4) * 16;
    const uint32_t bOff = (uint32_t)(wn * 32 + (((lane >> 4) << 3) | (lane & 7))) * ROWB
                        + (uint32_t)((lane >> 3) & 1) * 16;

    float acc[4][4][4];
    #pragma unroll
    for (int mt = 0; mt < 4; mt++)
        #pragma unroll
        for (int nt = 0; nt < 4; nt++)
            #pragma unroll
            for (int i = 0; i < 4; i++) acc[mt][nt][i] = 0.f;

    float4 rB[2];

    rB[0] = *reinterpret_cast<const float4*>(Wrow);
    rB[1] = *reinterpret_cast<const float4*>(Wrow + 4);
    {
        bf16 h0,h1,h2,h3,l0,l1,l2,l3;
        #pragma unroll
        for (int v = 0; v < 2; v++) {
            split2(rB[v].x, h0, l0); split2(rB[v].y, h1, l1);
            split2(rB[v].z, h2, l2); split2(rB[v].w, h3, l3);
            *reinterpret_cast<uint2*>(smem + 2 * W_ATILE + bsts + v * 8) = make_uint2(pk(h0,h1), pk(h2,h3));
            *reinterpret_cast<uint2*>(smem + 2 * W_ATILE + W_BTILE + bsts + v * 8) = make_uint2(pk(l0,l1), pk(l2,l3));
        }
    }
    w_a_stage_load(sb, Ahi, Alo, lda, 0, bm, tid);
    CP_COMMIT();
    if (nk > 1) w_a_stage_load(sb + W_STAGEB, Ahi, Alo, lda, 32, bm, tid);
    CP_COMMIT();
    if (nk > 1) {
        rB[0] = *reinterpret_cast<const float4*>(Wrow + 32);
        rB[1] = *reinterpret_cast<const float4*>(Wrow + 36);
    }

    for (int j = 0; j < nk; j++) {
        CP_WAIT1();
        __syncthreads();

        int jn = j + 2;
        if (jn < nk)
            w_a_stage_load(sb + (uint32_t)(jn % W_STAGES) * W_STAGEB, Ahi, Alo, lda, jn * 32, bm, tid);
        CP_COMMIT();

        const uint32_t st = sb + (uint32_t)(j % W_STAGES) * W_STAGEB;
        #pragma unroll
        for (int kk = 0; kk < 2; kk++) {
            uint32_t bh[2][4], bl[2][4];
            #pragma unroll
            for (int n2 = 0; n2 < 2; n2++) {
                uint32_t base = st + bOff + 2 * W_ATILE + (uint32_t)n2 * (16 * ROWB) + (uint32_t)kk * 32;
                ldsm_x4(bh[n2], base);
                ldsm_x4(bl[n2], base + W_BTILE);
            }
            #pragma unroll
            for (int mt = 0; mt < 4; mt++) {
                uint32_t ah[4], al[4];
                uint32_t base = st + aOff + (uint32_t)mt * (16 * ROWB) + (uint32_t)kk * 32;
                ldsm_x4(ah, base);
                ldsm_x4(al, base + W_ATILE);
                MMA_TERM_MAJOR(acc[mt], ah, al, bh, bl);
            }
        }

        if (j + 1 < nk) {
            uint32_t dst = (uint32_t)((j + 1) % W_STAGES) * W_STAGEB + 2 * W_ATILE + bsts;
            bf16 h0,h1,h2,h3,l0,l1,l2,l3;
            #pragma unroll
            for (int v = 0; v < 2; v++) {
                split2(rB[v].x, h0, l0); split2(rB[v].y, h1, l1);
                split2(rB[v].z, h2, l2); split2(rB[v].w, h3, l3);
                *reinterpret_cast<uint2*>(smem + dst + v * 8) = make_uint2(pk(h0,h1), pk(h2,h3));
                *reinterpret_cast<uint2*>(smem + dst + W_BTILE + v * 8) = make_uint2(pk(l0,l1), pk(l2,l3));
            }
        }
        if (j + 2 < nk) {
            const float* p = Wrow + (j + 2) * 32;
            rB[0] = *reinterpret_cast<const float4*>(p);
            rB[1] = *reinterpret_cast<const float4*>(p + 4);
        }
    }

    const int gr = lane >> 2;
    const int gc = (lane & 3) * 2;
    #pragma unroll
    for (int mt = 0; mt < 4; mt++) {
        int row0 = bm + wm * 64 + mt * 16 + gr;
        #pragma unroll
        for (int nt = 0; nt < 4; nt++) {
            int c = bn + wn * 32 + nt * 8 + gc;
            *reinterpret_cast<float2*>(C + (long long)row0 * ldc + c) =
                make_float2(acc[mt][nt][0], acc[mt][nt][1]);
            *reinterpret_cast<float2*>(C + (long long)(row0 + 8) * ldc + c) =
                make_float2(acc[mt][nt][2], acc[mt][nt][3]);
        }
    }
}

// === ATTENTION GEMM: 128x128, 256 thr, 2-stage, 2 CTAs/SM, single sync ======
// mode 1: causal scores -> fp32 C.  mode 2: causal PV -> bf16 split Chi/Clo.
#define NTA    256
#define A_ATILE  (128 * ROWB)
#define A_BTILE  (128 * ROWB)
#define A_STAGEB (2 * A_ATILE + 2 * A_BTILE)
#define A_SMEM   (2 * A_STAGEB)

__device__ __forceinline__ void stage_load_ab(
    uint32_t sdst,
    const bf16* __restrict__ Ahi, const bf16* __restrict__ Alo,
    const bf16* __restrict__ Bhi, const bf16* __restrict__ Blo,
    int lda, int ldb, int k0, int bm, int bn, int tid)
{
    #pragma unroll
    for (int i = 0; i < 2; i++) {
        int idx = tid + i * NTA;
        int r = idx >> 2, seg = (idx & 3) * 8;
        uint32_t soA = sdst + (uint32_t)r * ROWB + (uint32_t)seg * 2;
        long long gA = (long long)(bm + r) * lda + k0 + seg;
        CP16(soA,           Ahi + gA);
        CP16(soA + A_ATILE, Alo + gA);
        uint32_t soB = sdst + 2 * A_ATILE + (uint32_t)r * ROWB + (uint32_t)seg * 2;
        long long gB = (long long)(bn + r) * ldb + k0 + seg;
        CP16(soB,           Bhi + gB);
        CP16(soB + A_BTILE, Blo + gB);
    }
}

__global__ void __launch_bounds__(NTA, 2)
gemm_bf16_split(const bf16* __restrict__ Ahi, const bf16* __restrict__ Alo,
                const bf16* __restrict__ Bhi, const bf16* __restrict__ Blo,
                float* __restrict__ C, bf16* __restrict__ Chi, bf16* __restrict__ Clo,
                int K, int lda, int ldb, int ldc,
                long long sA, long long sB, long long sC, int mode)
{
    extern __shared__ char smem[];
    const int tid = threadIdx.x;
    const int lane = tid & 31;
    const int wid = tid >> 5;
    const int wm = wid & 1;
    const int wn = wid >> 1;

    const int bm = blockIdx.x * 128;
    const int bn = blockIdx.y * 128;
    if (mode == 1 && bn >= bm + 128) return;

    Ahi += (long long)blockIdx.z * sA;
    Alo += (long long)blockIdx.z * sA;
    Bhi += (long long)blockIdx.z * sB;
    Blo += (long long)blockIdx.z * sB;

    int kend = (mode == 2) ? min(K, bm + 128) : K;
    const int nk = kend / 32;

    const uint32_t sb = smem_u32(smem);

    const uint32_t aOff = (uint32_t)(wm * 64 + (lane & 15)) * ROWB + (uint32_t)(lane >> 4) * 16;
    const uint32_t bOff = (uint32_t)(wn * 32 + (((lane >> 4) << 3) | (lane & 7))) * ROWB
                        + (uint32_t)((lane >> 3) & 1) * 16;

    float acc[4][4][4];
    #pragma unroll
    for (int mt = 0; mt < 4; mt++)
        #pragma unroll
        for (int nt = 0; nt < 4; nt++)
            #pragma unroll
            for (int i = 0; i < 4; i++) acc[mt][nt][i] = 0.f;

    stage_load_ab(sb, Ahi, Alo, Bhi, Blo, lda, ldb, 0, bm, bn, tid);
    CP_COMMIT();

    for (int j = 0; j < nk; j++) {
        CP_WAIT0();
        __syncthreads();

        if (j + 1 < nk) {
            stage_load_ab(sb + (uint32_t)((j + 1) & 1) * A_STAGEB,
                          Ahi, Alo, Bhi, Blo, lda, ldb, (j + 1) * 32, bm, bn, tid);
            CP_COMMIT();
        }

        const uint32_t st = sb + (uint32_t)(j & 1) * A_STAGEB;
        #pragma unroll
        for (int kk = 0; kk < 2; kk++) {
            uint32_t bh[2][4], bl[2][4];
            #pragma unroll
            for (int n2 = 0; n2 < 2; n2++) {
                uint32_t base = st + bOff + 2 * A_ATILE + (uint32_t)n2 * (16 * ROWB) + (uint32_t)kk * 32;
                ldsm_x4(bh[n2], base);
                ldsm_x4(bl[n2], base + A_BTILE);
            }
            #pragma unroll
            for (int mt = 0; mt < 4; mt++) {
                uint32_t ah[4], al[4];
                uint32_t base = st + aOff + (uint32_t)mt * (16 * ROWB) + (uint32_t)kk * 32;
                ldsm_x4(ah, base);
                ldsm_x4(al, base + A_ATILE);
                MMA_TERM_MAJOR(acc[mt], ah, al, bh, bl);
            }
        }
    }

    const int gr = lane >> 2;
    const int gc = (lane & 3) * 2;
    if (mode == 2) {
        // fused fp32->bf16 split epilogue into Chi/Clo (stride ldc)
        bf16* chi = Chi + (long long)blockIdx.z * sC;
        bf16* clo = Clo + (long long)blockIdx.z * sC;
        #pragma unroll
        for (int mt = 0; mt < 4; mt++) {
            int row0 = bm + wm * 64 + mt * 16 + gr;
            #pragma unroll
            for (int nt = 0; nt < 4; nt++) {
                int c = bn + wn * 32 + nt * 8 + gc;
                bf16 ha, hb, la, lb;
                split2(acc[mt][nt][0], ha, la); split2(acc[mt][nt][1], hb, lb);
                *reinterpret_cast<uint32_t*>(chi + (long long)row0 * ldc + c) = pk(ha, hb);
                *reinterpret_cast<uint32_t*>(clo + (long long)row0 * ldc + c) = pk(la, lb);
                split2(acc[mt][nt][2], ha, la); split2(acc[mt][nt][3], hb, lb);
                *reinterpret_cast<uint32_t*>(chi + (long long)(row0 + 8) * ldc + c) = pk(ha, hb);
                *reinterpret_cast<uint32_t*>(clo + (long long)(row0 + 8) * ldc + c) = pk(la, lb);
            }
        }
    } else {
        float* cc = C + (long long)blockIdx.z * sC;
        #pragma unroll
        for (int mt = 0; mt < 4; mt++) {
            int row0 = bm + wm * 64 + mt * 16 + gr;
            #pragma unroll
            for (int nt = 0; nt < 4; nt++) {
                int c = bn + wn * 32 + nt * 8 + gc;
                *reinterpret_cast<float2*>(cc + (long long)row0 * ldc + c) =
                    make_float2(acc[mt][nt][0], acc[mt][nt][1]);
                *reinterpret_cast<float2*>(cc + (long long)(row0 + 8) * ldc + c) =
                    make_float2(acc[mt][nt][2], acc[mt][nt][3]);
            }
        }
    }
}

// ---------------- RMSNorm with fused split ----------------
__global__ void __launch_bounds__(256) rmsnorm_split_kernel(
    const float* __restrict__ x, const float* __restrict__ w,
    bf16* __restrict__ yhi, bf16* __restrict__ ylo)
{
    int s = blockIdx.x;
    const float* rowp = x + (long long)s * HID;
    int tid = threadIdx.x;

    float ss = 0.f;
    for (int i = tid; i < HID; i += 256) { float v = rowp[i]; ss += v * v; }
    __shared__ float red[256];
    red[tid] = ss; __syncthreads();
    for (int st = 128; st > 0; st >>= 1) { if (tid < st) red[tid] += red[tid + st]; __syncthreads(); }
    float inv = rsqrtf(red[0] / (float)HID + 1e-6f);

    bf16* oh = yhi + (long long)s * HID;
    bf16* ol = ylo + (long long)s * HID;
    for (int i = tid; i < HID; i += 256) {
        float v = rowp[i] * inv * w[i];
        bf16 h, l; split2(v, h, l);
        oh[i] = h; ol[i] = l;
    }
}

// ------------ fused residual add + RMSNorm + split ----------------
__global__ void __launch_bounds__(256) add_rms_split_kernel(
    float* __restrict__ h, const float* __restrict__ o, const float* __restrict__ w,
    bf16* __restrict__ yhi, bf16* __restrict__ ylo)
{
    int s = blockIdx.x;
    long long base = (long long)s * HID;
    int tid = threadIdx.x;
    __shared__ float v[HID];
    __shared__ float red[256];

    float ss = 0.f;
    for (int i = tid; i < HID; i += 256) {
        float t = h[base + i] + o[base + i];
        h[base + i] = t;
        v[i] = t;
        ss += t * t;
    }
    red[tid] = ss; __syncthreads();
    for (int st = 128; st > 0; st >>= 1) { if (tid < st) red[tid] += red[tid + st]; __syncthreads(); }
    float inv = rsqrtf(red[0] / (float)HID + 1e-6f);

    bf16* oh = yhi + base;
    bf16* ol = ylo + base;
    for (int i = tid; i < HID; i += 256) {
        float t = v[i] * inv * w[i];
        bf16 hh, ll; split2(t, hh, ll);
        oh[i] = hh; ol[i] = ll;
    }
}

// -------- RoPE q/k + coalesced V transpose ----------------
__global__ void __launch_bounds__(256) rope_v_kernel(
    const float* __restrict__ qkv,
    const float* __restrict__ cosT, const float* __restrict__ sinT,
    const int* __restrict__ pos_ids,
    bf16* __restrict__ qhi, bf16* __restrict__ qlo,
    bf16* __restrict__ khi, bf16* __restrict__ klo,
    bf16* __restrict__ vthi, bf16* __restrict__ vtlo)
{
    extern __shared__ uint32_t T[];
    int head = blockIdx.x;
    int st = blockIdx.y * 128;
    int tid = threadIdx.x;

    for (int i = tid; i < 128 * 128; i += 256) {
        int sl = i >> 7, d = i & 127;
        int s = st + sl;
        int pos = pos_ids[s];
        if (pos < 0) pos = 0;
        if (pos >= SEQ) pos = SEQ - 1;
        const float* rowp = qkv + (long long)s * (3 * HID);
        int idx = head * HD + d;
        float qv = rowp[idx];
        float kv = rowp[HID + idx];
        float vv = rowp[2 * HID + idx];
        float qo = (d < 64) ? -rowp[idx + 64] : rowp[idx - 64];
        float ko = (d < 64) ? -rowp[HID + idx + 64] : rowp[HID + idx - 64];
        float cd = cosT[(long long)pos * HD + d];
        float sd = sinT[(long long)pos * HD + d];
        float qr = qv * cd + qo * sd;
        float kr = kv * cd + ko * sd;
        long long qi = ((long long)head * SEQ + s) * HD + d;
        bf16 hh, ll;
        split2(qr, hh, ll); qhi[qi] = hh; qlo[qi] = ll;
        split2(kr, hh, ll); khi[qi] = hh; klo[qi] = ll;
        split2(vv, hh, ll);
        T[sl * 129 + d] = pk(hh, ll);
    }
    __syncthreads();
    for (int i = tid; i < 128 * 128; i += 256) {
        int d = i >> 7, sl = i & 127;
        uint32_t p = T[sl * 129 + d];
        long long vi = ((long long)head * HD + d) * SEQ + st + sl;
        vthi[vi] = __ushort_as_bfloat16((unsigned short)(p & 0xFFFF));
        vtlo[vi] = __ushort_as_bfloat16((unsigned short)(p >> 16));
    }
}

// ---------------- causal softmax with fused split (block-capped fill) -------
__global__ void __launch_bounds__(256) softmax_split_kernel(
    float* __restrict__ scores, bf16* __restrict__ phi, bf16* __restrict__ plo)
{
    int qrow = blockIdx.x;
    int head = blockIdx.y;
    long long off = ((long long)head * SEQ + qrow) * SEQ;
    float* rowp = scores + off;
    bf16* oh = phi + off;
    bf16* ol = plo + off;
    int n = qrow + 1;
    int blockend = ((qrow >> 7) + 1) << 7;    // PV never reads past this
    int tid = threadIdx.x;
    const float scale = 0.088388347648318447f;

    __shared__ float red[256];

    float m = -3.4e38f;
    for (int i = tid; i < n; i += 256) m = fmaxf(m, rowp[i] * scale);
    red[tid] = m; __syncthreads();
    for (int st = 128; st > 0; st >>= 1) { if (tid < st) red[tid] = fmaxf(red[tid], red[tid + st]); __syncthreads(); }
    m = red[0]; __syncthreads();

    float sum = 0.f;
    for (int i = tid; i < n; i += 256) {
        float e = expf(rowp[i] * scale - m);
        rowp[i] = e;
        sum += e;
    }
    red[tid] = sum; __syncthreads();
    for (int st = 128; st > 0; st >>= 1) { if (tid < st) red[tid] += red[tid + st]; __syncthreads(); }
    float inv = 1.f / red[0];

    for (int i = tid; i < n; i += 256) {
        float p = rowp[i] * inv;
        bf16 h, l; split2(p, h, l);
        oh[i] = h; ol[i] = l;
    }
    bf16 z = __float2bfloat16(0.f);
    for (int i = n + tid; i < blockend; i += 256) { oh[i] = z; ol[i] = z; }
}

// ---------------- elementwise ----------------
__global__ void __launch_bounds__(256) add_kernel(float* __restrict__ a, const float* __restrict__ b, int n)
{
    int i = blockIdx.x * 256 + threadIdx.x;
    if (i < n) a[i] += b[i];
}

__global__ void __launch_bounds__(256) silu_mul_split_kernel(
    const float* __restrict__ f, bf16* __restrict__ ghi, bf16* __restrict__ glo, int n)
{
    int i = blockIdx.x * 256 + threadIdx.x;
    if (i < n) {
        int s = i / INTER, c = i - s * INTER;
        long long base = (long long)s * (2 * INTER);
        float x = f[base + c];
        float v = x / (1.f + expf(-x)) * f[base + INTER + c];
        bf16 h, l; split2(v, h, l);
        ghi[i] = h; glo[i] = l;
    }
}

// ---------------- orchestration ----------------
static inline void launch_gemm_w(const bf16* Ahi, const bf16* Alo,
                                 const float* B1, const float* B2, int N1, float* C,
                                 int M, int N, int K, int lda, int ldb, int ldc)
{
    dim3 grid(M / 256, N / 128);
    gemm_wsplit<<<grid, NTW, W_SMEM>>>(Ahi, Alo, B1, B2, N1, C, K, lda, ldb, ldc);
}

static inline void launch_gemm_a(const bf16* Ahi, const bf16* Alo,
                                 const bf16* Bhi, const bf16* Blo,
                                 float* C, bf16* Chi, bf16* Clo,
                                 int M, int N, int K, int lda, int ldb, int ldc,
                                 long long sA, long long sB, long long sC, int batch, int mode)
{
    dim3 grid(M / 128, N / 128, batch);
    gemm_bf16_split<<<grid, NTA, A_SMEM>>>(Ahi, Alo, Bhi, Blo, C, Chi, Clo,
                                           K, lda, ldb, ldc, sA, sB, sC, mode);
}

extern "C" void kernel_launch(void* const* d_in, const int* in_sizes, int n_in,
                              void* d_out, int out_size)
{
    const float* x      = (const float*)d_in[0];
    const int*   pos    = (const int*)d_in[1];
    const float* qkv_w  = (const float*)d_in[2];
    const float* o_w    = (const float*)d_in[3];
    const float* gate_w = (const float*)d_in[4];
    const float* up_w   = (const float*)d_in[5];
    const float* down_w = (const float*)d_in[6];
    const float* ln1_w  = (const float*)d_in[7];
    const float* ln2_w  = (const float*)d_in[8];
    const float* cosT   = (const float*)d_in[9];
    const float* sinT   = (const float*)d_in[10];
    float* h = (float*)d_out;

    cudaFuncSetAttribute(gemm_wsplit, cudaFuncAttributeMaxDynamicSharedMemorySize, W_SMEM);
    cudaFuncSetAttribute(gemm_bf16_split, cudaFuncAttributeMaxDynamicSharedMemorySize, A_SMEM);
    cudaFuncSetAttribute(rope_v_kernel, cudaFuncAttributeMaxDynamicSharedMemorySize, 128 * 129 * 4);

    float *o, *qkv, *sc, *f;
    bf16 *yhi, *ylo, *qhi, *qlo, *khi, *klo, *vthi, *vtlo, *phi, *plo, *ghi, *glo;
    cudaGetSymbolAddress((void**)&o, g_o);
    cudaGetSymbolAddress((void**)&qkv, g_qkv);
    cudaGetSymbolAddress((void**)&sc, g_sc);
    cudaGetSymbolAddress((void**)&f, g_f);
    cudaGetSymbolAddress((void**)&yhi, g_yhi);
    cudaGetSymbolAddress((void**)&ylo, g_ylo);
    cudaGetSymbolAddress((void**)&qhi, g_qhi);
    cudaGetSymbolAddress((void**)&qlo, g_qlo);
    cudaGetSymbolAddress((void**)&khi, g_khi);
    cudaGetSymbolAddress((void**)&klo, g_klo);
    cudaGetSymbolAddress((void**)&vthi, g_vthi);
    cudaGetSymbolAddress((void**)&vtlo, g_vtlo);
    cudaGetSymbolAddress((void**)&phi, g_phi);
    cudaGetSymbolAddress((void**)&plo, g_plo);
    cudaGetSymbolAddress((void**)&ghi, g_ghi);
    cudaGetSymbolAddress((void**)&glo, g_glo);

    cudaMemcpyAsync(h, x, sizeof(float) * SEQ * HID, cudaMemcpyDeviceToDevice, 0);

    const int nEl = SEQ * HID;
    const int nElI = SEQ * INTER;
    const int BIGN = 1 << 30;

    rmsnorm_split_kernel<<<SEQ, 256>>>(h, ln1_w, yhi, ylo);

    for (int L = 0; L < NL; L++) {
        const float* qw = qkv_w  + (size_t)L * 3 * HID * HID;
        const float* ow = o_w    + (size_t)L * HID * HID;
        const float* gw = gate_w + (size_t)L * INTER * HID;
        const float* uw = up_w   + (size_t)L * INTER * HID;
        const float* dw = down_w + (size_t)L * HID * INTER;

        // ---- attention ----
        launch_gemm_w(yhi, ylo, qw, qw, BIGN, qkv, SEQ, 3 * HID, HID, HID, HID, 3 * HID);

        rope_v_kernel<<<dim3(NH, SEQ / 128), 256, 128 * 129 * 4>>>(
            qkv, cosT, sinT, pos, qhi, qlo, khi, klo, vthi, vtlo);

        // scores (mode 1, fp32 out)
        launch_gemm_a(qhi, qlo, khi, klo, sc, 0, 0, SEQ, SEQ, HD, HD, HD, SEQ,
                      (long long)SEQ * HD, (long long)SEQ * HD, (long long)SEQ * SEQ, NH, 1);

        softmax_split_kernel<<<dim3(SEQ, NH), 256>>>(sc, phi, plo);

        // PV (mode 2, bf16 split out directly into yhi/ylo)
        launch_gemm_a(phi, plo, vthi, vtlo, 0, yhi, ylo, SEQ, HD, SEQ, SEQ, SEQ, HID,
                      (long long)SEQ * SEQ, (long long)HD * SEQ, (long long)HD, NH, 2);

        launch_gemm_w(yhi, ylo, ow, ow, BIGN, o, SEQ, HID, HID, HID, HID, HID);

        add_rms_split_kernel<<<SEQ, 256>>>(h, o, ln2_w + (size_t)L * HID, yhi, ylo);

        // ---- MLP: fused gate|up ----
        launch_gemm_w(yhi, ylo, gw, uw, INTER, f, SEQ, 2 * INTER, HID, HID, HID, 2 * INTER);

        silu_mul_split_kernel<<<nElI / 256, 256>>>(f, ghi, glo, nElI);

        launch_gemm_w(ghi, glo, dw, dw, BIGN, o, SEQ, HID, INTER, INTER, INTER, HID);

        if (L < NL - 1) {
            add_rms_split_kernel<<<SEQ, 256>>>(h, o, ln1_w + (size_t)(L + 1) * HID, yhi, ylo);
        } else {
            add_kernel<<<nEl / 256, 256>>>(h, o, nEl);
        }
    }
}